// round 9
// baseline (speedup 1.0000x reference)
#include <cuda_runtime.h>
#include <cuda_bf16.h>
#include <math.h>

#define A_TOT 147456      // 128*128*9 anchors
#define HW    16384
#define GW    128
#define CIN   512
#define KTOT  4608        // 512*9
#define KSPLIT 16
#define KCH   288         // KTOT/KSPLIT
#define NCOL  1280        // original columns: 512 pos-bbox + 256 pos-score + 512 neg-score
#define NU2   1088        // max unique columns padded (513 + 4*128 -> 1025 -> 1088)
#define NBLK  576         // A_TOT/256
#define STEP  (2048.0f/127.0f)

__constant__ float d_whw[9] = {128.0f, 181.01933598375618f, 90.50966799187809f,
                               256.0f, 362.03867196751236f, 181.01933598375618f,
                               512.0f, 724.0773439350247f, 362.03867196751236f};
__constant__ float d_whh[9] = {128.0f, 90.50966799187809f, 181.01933598375618f,
                               256.0f, 181.01933598375618f, 362.03867196751236f,
                               512.0f, 362.03867196751236f, 724.0773439350247f};

// ---------------- static device scratch ----------------
__device__ float d_maxIou[A_TOT];
__device__ int   d_tgtIdx[A_TOT];
__device__ int   d_posIdx[128];
__device__ int   d_posValid[128];
__device__ int   d_negValid[256];
__device__ int   d_nPos;
__device__ int   d_Upad;              // padded unique-column count (multiple of 64)
__device__ int   d_colPos[NCOL];      // spatial position per ORIGINAL column (valid only)
__device__ int   d_colMeta[NCOL];     // weight row per original column (valid only)
__device__ int   d_uniqPos[NU2];      // spatial position per UNIQUE column
__device__ float d_Bg[KTOT * NU2];    // gathered patches [k][u]
__device__ float d_hp[KSPLIT * NU2 * CIN]; // GEMM partials [ks][u][m]
__device__ float d_val[NCOL];

// ---------------- packed fp32 FMA ----------------
__device__ __forceinline__ unsigned long long ffma2(unsigned long long a,
                                                    unsigned long long b,
                                                    unsigned long long c) {
    unsigned long long d;
    asm("fma.rn.f32x2 %0, %1, %2, %3;" : "=l"(d) : "l"(a), "l"(b), "l"(c));
    return d;
}

// ---------------- phase A: IoU matching ----------------
__global__ void iou_kernel(const float* __restrict__ target) {
    __shared__ float4 tg[64];
    int t = threadIdx.x;
    if (t < 64) tg[t] = ((const float4*)target)[t];
    __syncthreads();
    int a = blockIdx.x * 256 + t;
    int k = a % 9;
    int q = a / 9;
    int wq = q & 127;
    int hq = q >> 7;
    float x1 = hq * STEP;
    float y1 = wq * STEP;
    float x2 = x1 + d_whw[k];
    float y2 = y1 + d_whh[k];
    float areaA = (x2 - x1) * (y2 - y1);

    float best = -1.0f;
    int bi = 0;
    #pragma unroll 4
    for (int i = 0; i < 64; i++) {
        float4 b = tg[i];
        float lx = fmaxf(b.x, x1), ly = fmaxf(b.y, y1);
        float rx = fminf(b.z, x2), ry = fminf(b.w, y2);
        float iw = fmaxf(rx - lx, 0.0f), ih = fmaxf(ry - ly, 0.0f);
        float inter = iw * ih;
        float at = (b.z - b.x) * (b.w - b.y);
        float iou = inter / (at + areaA - inter);
        if (iou > best) { best = iou; bi = i; }   // first-max == jnp.argmax
    }
    d_maxIou[a] = best;
    d_tgtIdx[a] = bi;
}

// ---------------- fallback sort helper (1024 threads) ----------------
__device__ __forceinline__ void bitonic2048(unsigned long long* s) {
    int t = threadIdx.x;
    for (int k = 2; k <= 2048; k <<= 1) {
        for (int j = k >> 1; j > 0; j >>= 1) {
            __syncthreads();
            #pragma unroll
            for (int base = 0; base < 2048; base += 1024) {
                int i = base + t;
                int ixj = i ^ j;
                if (ixj > i) {
                    unsigned long long va = s[i], vb = s[ixj];
                    bool sw = ((i & k) == 0) ? (va < vb) : (va > vb);
                    if (sw) { s[i] = vb; s[ixj] = va; }
                }
            }
        }
    }
    __syncthreads();
}

// ---------------- phase B: ONE-kernel selection + column tables ----------------
__global__ void selection_kernel() {   // 1 block x 1024 threads
    __shared__ unsigned long long pKeys[2048];
    __shared__ int zIdx[256];
    __shared__ int wz[32], wp[32];
    __shared__ int zTot, pTot, zBase, pBase;
    int t = threadIdx.x, lane = t & 31, w = t >> 5;
    if (t == 0) { zTot = 0; pTot = 0; }
    __syncthreads();

    for (int it = 0; it < A_TOT / 1024; it++) {
        int a = it * 1024 + t;
        float best = d_maxIou[a];
        bool zf = (zTot < 256);                    // uniform (post-sync read)
        bool z = zf && (best < 0.3f) && ((1.0f - best) == 1.0f);  // exact ref tie-class
        bool p = (best > 0.7f);
        unsigned zb = __ballot_sync(0xFFFFFFFFu, z);
        unsigned pb = __ballot_sync(0xFFFFFFFFu, p);
        if (lane == 0) { wz[w] = __popc(zb); wp[w] = __popc(pb); }
        __syncthreads();
        if (w == 0) {
            int vz = wz[lane], vp = wp[lane];
            int sz = vz, sp = vp;
            #pragma unroll
            for (int o = 1; o < 32; o <<= 1) {
                int xz = __shfl_up_sync(0xFFFFFFFFu, sz, o);
                int xp = __shfl_up_sync(0xFFFFFFFFu, sp, o);
                if (lane >= o) { sz += xz; sp += xp; }
            }
            wz[lane] = sz - vz;                    // exclusive prefix
            wp[lane] = sp - vp;
            if (lane == 31) {
                zBase = zTot; pBase = pTot;
                zTot = zTot + sz; pTot = pTot + sp;
            }
        }
        __syncthreads();
        if (z) {
            int r = zBase + wz[w] + __popc(zb & ((1u << lane) - 1));
            if (r < 256) zIdx[r] = a;
        }
        if (p) {
            int r = pBase + wp[w] + __popc(pb & ((1u << lane) - 1));
            if (r < 2048)
                pKeys[r] = (((unsigned long long)__float_as_uint(best) << 32) |
                            (0xFFFFFFFFu - (unsigned)a));
        }
        __syncthreads();
    }

    int cnt = pTot;
    int npos = cnt < 128 ? cnt : 128;
    int K = 256 - npos;
    if (t == 0) {
        d_nPos = npos;
        int U = 513 + 4 * npos;
        d_Upad = (U + 63) & ~63;
    }
    if (cnt > 128) {
        // rare fallback: exact top-128 by (iou desc, index asc)
        int stored = cnt < 2048 ? cnt : 2048;
        for (int i = t; i < 2048; i += 1024)
            if (i >= stored) pKeys[i] = 0ULL;
        __syncthreads();
        bitonic2048(pKeys);
    }
    __syncthreads();
    if (t < 128) {
        int valid = (t < npos);
        d_posValid[t] = valid;
        if (valid) {
            int p = (int)(0xFFFFFFFFu - (unsigned)(pKeys[t] & 0xFFFFFFFFULL));
            d_posIdx[t] = p;
            int sb = (4 * p) & 16383;
            int ssc = (2 * p) & 16383;
            int cb = p >> 12;
            int cs = 36 + (p >> 13);
            #pragma unroll
            for (int e = 0; e < 4; e++) {
                d_colPos[4 * t + e] = sb + e;
                d_colMeta[4 * t + e] = cb;
            }
            #pragma unroll
            for (int e = 0; e < 2; e++) {
                d_colPos[512 + 2 * t + e] = ssc + e;
                d_colMeta[512 + 2 * t + e] = cs;
            }
        }
    }
    if (t < 256) {
        d_negValid[t] = (t < K);
        if (t < K) {
            int a = zIdx[t];
            int ss = (2 * a) & 16383;
            int cs = 36 + (a >> 13);
            d_colPos[768 + 2 * t] = ss;         d_colMeta[768 + 2 * t] = cs;
            d_colPos[768 + 2 * t + 1] = ss + 1; d_colMeta[768 + 2 * t + 1] = cs;
        }
    }
    __syncthreads();
    // unique-position table: u=0 shared by all invalid cols; u>=1 valid cols in order
    for (int u = t; u < NU2; u += 1024) {
        int pos = 0;
        if (u >= 1) {
            int v = u - 1;
            if (v < 4 * npos)              pos = d_colPos[v];
            else if (v < 6 * npos)         pos = d_colPos[512 + (v - 4 * npos)];
            else if (v < 6 * npos + 2 * K) pos = d_colPos[768 + (v - 6 * npos)];
        }
        d_uniqPos[u] = pos;
    }
}

// ---------------- gather 3x3 input patches: Bg[k][u] ----------------
__global__ void gather_kernel(const float* __restrict__ x) {
    int t = threadIdx.x;
    int n = blockIdx.x * 32 + (t & 31);     // grid.x = NU2/32
    int k = blockIdx.y * 8 + (t >> 5);      // grid.y = KTOT/8
    if (n >= d_Upad) return;
    int s = d_uniqPos[n];
    int ci = k / 9;
    int r  = k - ci * 9;
    int ky = r / 3;
    int kx = r - ky * 3;
    int y  = (s >> 7) + ky - 1;
    int xx = (s & 127) + kx - 1;
    float v = 0.0f;
    if (((unsigned)y < 128u) && ((unsigned)xx < 128u))
        v = x[ci * HW + y * GW + xx];
    d_Bg[k * NU2 + n] = v;
}

// ---------------- GEMM: partials, FFMA2, pipelined 64x64 tile / 64 thr / 8x8 regs ----------------
__global__ __launch_bounds__(64, 8)
void gemm_kernel(const float* __restrict__ W) {
    int n0 = blockIdx.x * 64;
    if (n0 >= d_Upad) return;               // dedup early-exit (graph-safe, data-driven)
    __shared__ float2 As2[16][64];          // A duplicated pairs {v,v}, [k][m]
    __shared__ float  Bs[16][64];           // [k][n]
    int tid = threadIdx.x;
    int tx = tid & 7, ty = tid >> 3;
    int m0 = blockIdx.y * 64;
    int ks = blockIdx.z;
    int kbase = ks * KCH;

    const float* Ap = W + (m0 + tid) * KTOT + kbase;
    int bk = tid >> 2;
    int bn = (tid & 3) * 16;
    const float* Bp = d_Bg + (kbase + bk) * NU2 + n0 + bn;

    unsigned long long acc[8][4];
    #pragma unroll
    for (int i = 0; i < 8; i++)
        #pragma unroll
        for (int j = 0; j < 4; j++) acc[i][j] = 0ULL;

    // prologue load
    float4 a0 = *(const float4*)(Ap);
    float4 a1 = *(const float4*)(Ap + 4);
    float4 a2 = *(const float4*)(Ap + 8);
    float4 a3 = *(const float4*)(Ap + 12);
    float4 b0 = *(const float4*)(Bp);
    float4 b1 = *(const float4*)(Bp + 4);
    float4 b2 = *(const float4*)(Bp + 8);
    float4 b3 = *(const float4*)(Bp + 12);

    for (int k0 = 0; k0 < KCH; k0 += 16) {
        __syncthreads();
        {
            float va[16] = {a0.x, a0.y, a0.z, a0.w, a1.x, a1.y, a1.z, a1.w,
                            a2.x, a2.y, a2.z, a2.w, a3.x, a3.y, a3.z, a3.w};
            #pragma unroll
            for (int j = 0; j < 16; j++) As2[j][tid] = make_float2(va[j], va[j]);
        }
        *(float4*)&Bs[bk][bn]      = b0;
        *(float4*)&Bs[bk][bn + 4]  = b1;
        *(float4*)&Bs[bk][bn + 8]  = b2;
        *(float4*)&Bs[bk][bn + 12] = b3;
        __syncthreads();
        // prefetch next chunk while computing this one
        if (k0 + 16 < KCH) {
            const float* ap = Ap + k0 + 16;
            const float* bp = Bp + (k0 + 16) * NU2;
            a0 = *(const float4*)(ap);
            a1 = *(const float4*)(ap + 4);
            a2 = *(const float4*)(ap + 8);
            a3 = *(const float4*)(ap + 12);
            b0 = *(const float4*)(bp);
            b1 = *(const float4*)(bp + 4);
            b2 = *(const float4*)(bp + 8);
            b3 = *(const float4*)(bp + 12);
        }
        #pragma unroll
        for (int kk = 0; kk < 16; kk++) {
            const ulonglong2* ar = (const ulonglong2*)(&As2[kk][ty * 8]);
            ulonglong2 A0 = ar[0], A1 = ar[1], A2 = ar[2], A3 = ar[3];
            const ulonglong2* br = (const ulonglong2*)(&Bs[kk][tx * 8]);
            ulonglong2 B0 = br[0], B1 = br[1];
            unsigned long long am[8] = {A0.x, A0.y, A1.x, A1.y,
                                        A2.x, A2.y, A3.x, A3.y};
            unsigned long long bv[4] = {B0.x, B0.y, B1.x, B1.y};
            #pragma unroll
            for (int mi = 0; mi < 8; mi++)
                #pragma unroll
                for (int nj = 0; nj < 4; nj++)
                    acc[mi][nj] = ffma2(am[mi], bv[nj], acc[mi][nj]);
        }
    }
    // transposed partial store: d_hp[ks][u][m]
    #pragma unroll
    for (int j = 0; j < 8; j++) {
        float v[8];
        #pragma unroll
        for (int mi = 0; mi < 8; mi++) {
            float2 pr = *(float2*)&acc[mi][j >> 1];
            v[mi] = (j & 1) ? pr.y : pr.x;
        }
        float4* o = (float4*)(d_hp + (ks * NU2 + n0 + tx * 8 + j) * CIN + m0 + ty * 8);
        o[0] = make_float4(v[0], v[1], v[2], v[3]);
        o[1] = make_float4(v[4], v[5], v[6], v[7]);
    }
}

// ---------------- per-column 1x1 conv dot (fused partial-reduce + bias + relu) ----------------
__global__ void coldot_kernel(const float* __restrict__ bw, const float* __restrict__ bb,
                              const float* __restrict__ sw, const float* __restrict__ sb,
                              const float* __restrict__ conv_b) {
    int col = blockIdx.x * 8 + (threadIdx.x >> 5);
    int lane = threadIdx.x & 31;
    int npos = d_nPos;
    int u;
    if (col < 512)      { int t = col >> 2;         u = (t < npos) ? 1 + col : 0; }
    else if (col < 768) { int t = (col - 512) >> 1; u = (t < npos) ? 1 + 4 * npos + (col - 512) : 0; }
    else                { int g = (col - 768) >> 1; u = (g < 256 - npos) ? 1 + 6 * npos + (col - 768) : 0; }
    if (u == 0) return;   // invalid column: never read by the loss
    int meta = d_colMeta[col];
    const float* w;
    float b;
    if (meta < 36) { w = bw + meta * 512; b = bb[meta]; }
    else           { w = sw + (meta - 36) * 512; b = sb[meta - 36]; }
    const float4* wv = (const float4*)w;
    const float4* bias4 = (const float4*)conv_b;
    float s = 0.0f;
    for (int i = lane; i < 128; i += 32) {
        float4 a = bias4[i];
        #pragma unroll
        for (int ks = 0; ks < KSPLIT; ks++) {
            const float4* hp4 = (const float4*)(d_hp + (ks * NU2 + u) * CIN);
            float4 hv = hp4[i];
            a.x += hv.x; a.y += hv.y; a.z += hv.z; a.w += hv.w;
        }
        a.x = fmaxf(a.x, 0.0f); a.y = fmaxf(a.y, 0.0f);
        a.z = fmaxf(a.z, 0.0f); a.w = fmaxf(a.w, 0.0f);
        float4 ww = wv[i];
        s += a.x * ww.x + a.y * ww.y + a.z * ww.z + a.w * ww.w;
    }
    #pragma unroll
    for (int o = 16; o > 0; o >>= 1) s += __shfl_xor_sync(0xFFFFFFFFu, s, o);
    if (lane == 0) d_val[col] = fmaxf(s + b, 0.0f);
}

// ---------------- loss ----------------
__global__ void loss_kernel(const float* __restrict__ target, float* __restrict__ out) {
    __shared__ float rce[256], rsl[256], rvc[256];
    int t = threadIdx.x;
    float ce = 0.0f, sl = 0.0f, vc = 0.0f;
    if (t < 128 && d_posValid[t]) {
        float s0 = d_val[512 + 2 * t], s1 = d_val[512 + 2 * t + 1];
        float m = fmaxf(s0, s1);
        float lse = m + logf(expf(s0 - m) + expf(s1 - m));
        ce += lse - s0;
        vc += 1.0f;
        int p = d_posIdx[t];
        int k = p % 9;
        int q = p / 9;
        int wq = q & 127;
        int hq = q >> 7;
        float ax1 = hq * STEP, ay1 = wq * STEP;
        float aw = d_whw[k], ah = d_whh[k];
        float acx = ax1 + aw * 0.5f, acy = ay1 + ah * 0.5f;
        float4 tb = ((const float4*)target)[d_tgtIdx[p]];
        float bw_ = tb.z - tb.x, bh_ = tb.w - tb.y;
        float bcx = tb.x + bw_ * 0.5f, bcy = tb.y + bh_ * 0.5f;
        float tr[4] = {(bcx - acx) / aw, (bcy - acy) / ah,
                       logf(bw_ / aw), logf(bh_ / ah)};
        #pragma unroll
        for (int e = 0; e < 4; e++) {
            float d = d_val[4 * t + e] - tr[e];
            float ad = fabsf(d);
            sl += (ad < 1.0f) ? 0.5f * d * d : (ad - 0.5f);
        }
    }
    if (t < 256 && d_negValid[t]) {
        float s0 = d_val[768 + 2 * t], s1 = d_val[768 + 2 * t + 1];
        float m = fmaxf(s0, s1);
        float lse = m + logf(expf(s0 - m) + expf(s1 - m));
        ce += lse - s1;
        vc += 1.0f;
    }
    rce[t] = ce; rsl[t] = sl; rvc[t] = vc;
    __syncthreads();
    for (int s2 = 128; s2 > 0; s2 >>= 1) {
        if (t < s2) { rce[t] += rce[t + s2]; rsl[t] += rsl[t + s2]; rvc[t] += rvc[t + s2]; }
        __syncthreads();
    }
    if (t == 0) {
        float np = (float)d_nPos;
        float score_loss = rce[0] / fmaxf(rvc[0], 1.0f);
        float reg_loss = rsl[0] / fmaxf(np * 4.0f, 1.0f);
        out[0] = score_loss + 10.0f * reg_loss;
    }
}

// ---------------- launch ----------------
extern "C" void kernel_launch(void* const* d_in, const int* in_sizes, int n_in,
                              void* d_out, int out_size) {
    const float* x       = (const float*)d_in[0];
    const float* target  = (const float*)d_in[1];
    const float* conv_w  = (const float*)d_in[2];
    const float* conv_b  = (const float*)d_in[3];
    const float* bbox_w  = (const float*)d_in[4];
    const float* bbox_b  = (const float*)d_in[5];
    const float* score_w = (const float*)d_in[6];
    const float* score_b = (const float*)d_in[7];
    float* out = (float*)d_out;

    iou_kernel<<<NBLK, 256>>>(target);
    selection_kernel<<<1, 1024>>>();
    gather_kernel<<<dim3(NU2 / 32, KTOT / 8), 256>>>(x);
    gemm_kernel<<<dim3(NU2 / 64, CIN / 64, KSPLIT), 64>>>(conv_w);
    coldot_kernel<<<NCOL / 8, 256>>>(bbox_w, bbox_b, score_w, score_b, conv_b);
    loss_kernel<<<1, 256>>>(target, out);
}

// round 11
// speedup vs baseline: 1.5281x; 1.5281x over previous
#include <cuda_runtime.h>
#include <cuda_bf16.h>
#include <math.h>
#include <stdint.h>

#define A_TOT 147456      // 128*128*9 anchors
#define HW    16384
#define GW    128
#define CIN   512
#define KTOT  4608        // 512*9
#define K3    13824       // 3*KTOT (bf16-split expanded K)
#define KSPLIT 4
#define KQ    3456        // K3/KSPLIT
#define BK    64
#define NCHUNK2 54        // KQ/BK
#define NCOL  1280
#define NU2   1088        // max unique columns padded (17 tiles of 64)
#define NBLK  576
#define STEP  (2048.0f/127.0f)
#define ASTRIDE 72        // smem row stride in halves (64 + 8 pad)

__constant__ float d_whw[9] = {128.0f, 181.01933598375618f, 90.50966799187809f,
                               256.0f, 362.03867196751236f, 181.01933598375618f,
                               512.0f, 724.0773439350247f, 362.03867196751236f};
__constant__ float d_whh[9] = {128.0f, 90.50966799187809f, 181.01933598375618f,
                               256.0f, 181.01933598375618f, 362.03867196751236f,
                               512.0f, 362.03867196751236f, 724.0773439350247f};

// ---------------- static device scratch ----------------
__device__ float d_maxIou[A_TOT];
__device__ int   d_tgtIdx[A_TOT];
__device__ int   d_posIdx[128];
__device__ int   d_posValid[128];
__device__ int   d_negValid[256];
__device__ int   d_nPos;
__device__ int   d_Upad;
__device__ int   d_colPos[NCOL];
__device__ int   d_colMeta[NCOL];
__device__ int   d_uniqPos[NU2];
__device__ __align__(16) __nv_bfloat16 d_Wc[(size_t)CIN * K3];   // weights split [m][k']
__device__ __align__(16) __nv_bfloat16 d_Bc[(size_t)NU2 * K3];   // patches split [u][k']
__device__ float d_hp[KSPLIT * NU2 * CIN];                        // partials [ks][u][m]
__device__ float d_val[NCOL];

__device__ __forceinline__ uint32_t smem_u32(const void* p) {
    uint32_t a;
    asm("{ .reg .u64 t; cvta.to.shared.u64 t, %1; cvt.u32.u64 %0, t; }" : "=r"(a) : "l"(p));
    return a;
}

// ---------------- phase A: IoU matching ----------------
__global__ void iou_kernel(const float* __restrict__ target) {
    __shared__ float4 tg[64];
    int t = threadIdx.x;
    if (t < 64) tg[t] = ((const float4*)target)[t];
    __syncthreads();
    int a = blockIdx.x * 256 + t;
    int k = a % 9;
    int q = a / 9;
    int wq = q & 127;
    int hq = q >> 7;
    float x1 = hq * STEP;
    float y1 = wq * STEP;
    float x2 = x1 + d_whw[k];
    float y2 = y1 + d_whh[k];
    float areaA = (x2 - x1) * (y2 - y1);
    float best = -1.0f;
    int bi = 0;
    #pragma unroll 4
    for (int i = 0; i < 64; i++) {
        float4 b = tg[i];
        float lx = fmaxf(b.x, x1), ly = fmaxf(b.y, y1);
        float rx = fminf(b.z, x2), ry = fminf(b.w, y2);
        float iw = fmaxf(rx - lx, 0.0f), ih = fmaxf(ry - ly, 0.0f);
        float inter = iw * ih;
        float at = (b.z - b.x) * (b.w - b.y);
        float iou = inter / (at + areaA - inter);
        if (iou > best) { best = iou; bi = i; }   // first-max == jnp.argmax
    }
    d_maxIou[a] = best;
    d_tgtIdx[a] = bi;
}

// ---------------- fallback sort (1024 threads) ----------------
__device__ __forceinline__ void bitonic2048(unsigned long long* s) {
    int t = threadIdx.x;
    for (int k = 2; k <= 2048; k <<= 1) {
        for (int j = k >> 1; j > 0; j >>= 1) {
            __syncthreads();
            #pragma unroll
            for (int base = 0; base < 2048; base += 1024) {
                int i = base + t;
                int ixj = i ^ j;
                if (ixj > i) {
                    unsigned long long va = s[i], vb = s[ixj];
                    bool sw = ((i & k) == 0) ? (va < vb) : (va > vb);
                    if (sw) { s[i] = vb; s[ixj] = va; }
                }
            }
        }
    }
    __syncthreads();
}

// ---------------- phase B: one-kernel selection + column tables ----------------
__global__ void selection_kernel() {   // 1 block x 1024
    __shared__ unsigned long long pKeys[2048];
    __shared__ int zIdx[256];
    __shared__ int wz[32], wp[32];
    __shared__ int zTot, pTot, zBase, pBase;
    int t = threadIdx.x, lane = t & 31, w = t >> 5;
    if (t == 0) { zTot = 0; pTot = 0; }
    __syncthreads();
    for (int it = 0; it < A_TOT / 1024; it++) {
        int a = it * 1024 + t;
        float best = d_maxIou[a];
        bool zf = (zTot < 256);
        bool z = zf && (best < 0.3f) && ((1.0f - best) == 1.0f);  // exact ref tie-class
        bool p = (best > 0.7f);
        unsigned zb = __ballot_sync(0xFFFFFFFFu, z);
        unsigned pb = __ballot_sync(0xFFFFFFFFu, p);
        if (lane == 0) { wz[w] = __popc(zb); wp[w] = __popc(pb); }
        __syncthreads();
        if (w == 0) {
            int vz = wz[lane], vp = wp[lane];
            int sz = vz, sp = vp;
            #pragma unroll
            for (int o = 1; o < 32; o <<= 1) {
                int xz = __shfl_up_sync(0xFFFFFFFFu, sz, o);
                int xp = __shfl_up_sync(0xFFFFFFFFu, sp, o);
                if (lane >= o) { sz += xz; sp += xp; }
            }
            wz[lane] = sz - vz;
            wp[lane] = sp - vp;
            if (lane == 31) {
                zBase = zTot; pBase = pTot;
                zTot = zTot + sz; pTot = pTot + sp;
            }
        }
        __syncthreads();
        if (z) {
            int r = zBase + wz[w] + __popc(zb & ((1u << lane) - 1));
            if (r < 256) zIdx[r] = a;
        }
        if (p) {
            int r = pBase + wp[w] + __popc(pb & ((1u << lane) - 1));
            if (r < 2048)
                pKeys[r] = (((unsigned long long)__float_as_uint(best) << 32) |
                            (0xFFFFFFFFu - (unsigned)a));
        }
        __syncthreads();
    }
    int cnt = pTot;
    int npos = cnt < 128 ? cnt : 128;
    int K = 256 - npos;
    if (t == 0) {
        d_nPos = npos;
        int U = 513 + 4 * npos;
        d_Upad = (U + 63) & ~63;
    }
    if (cnt > 128) {
        int stored = cnt < 2048 ? cnt : 2048;
        for (int i = t; i < 2048; i += 1024)
            if (i >= stored) pKeys[i] = 0ULL;
        __syncthreads();
        bitonic2048(pKeys);
    }
    __syncthreads();
    if (t < 128) {
        int valid = (t < npos);
        d_posValid[t] = valid;
        if (valid) {
            int p = (int)(0xFFFFFFFFu - (unsigned)(pKeys[t] & 0xFFFFFFFFULL));
            d_posIdx[t] = p;
            int sb = (4 * p) & 16383;
            int ssc = (2 * p) & 16383;
            int cb = p >> 12;
            int cs = 36 + (p >> 13);
            #pragma unroll
            for (int e = 0; e < 4; e++) {
                d_colPos[4 * t + e] = sb + e;
                d_colMeta[4 * t + e] = cb;
            }
            #pragma unroll
            for (int e = 0; e < 2; e++) {
                d_colPos[512 + 2 * t + e] = ssc + e;
                d_colMeta[512 + 2 * t + e] = cs;
            }
        }
    }
    if (t < 256) {
        d_negValid[t] = (t < K);
        if (t < K) {
            int a = zIdx[t];
            int ss = (2 * a) & 16383;
            int cs = 36 + (a >> 13);
            d_colPos[768 + 2 * t] = ss;         d_colMeta[768 + 2 * t] = cs;
            d_colPos[768 + 2 * t + 1] = ss + 1; d_colMeta[768 + 2 * t + 1] = cs;
        }
    }
    __syncthreads();
    for (int u = t; u < NU2; u += 1024) {
        int pos = 0;
        if (u >= 1) {
            int v = u - 1;
            if (v < 4 * npos)              pos = d_colPos[v];
            else if (v < 6 * npos)         pos = d_colPos[512 + (v - 4 * npos)];
            else if (v < 6 * npos + 2 * K) pos = d_colPos[768 + (v - 6 * npos)];
        }
        d_uniqPos[u] = pos;
    }
}

// ---------------- weight bf16-split: Wc[m][k'] (t0=hi, t1=hi, t2=lo) ----------------
__global__ void wconv_kernel(const float* __restrict__ W) {
    int idx = blockIdx.x * 256 + threadIdx.x;   // CIN*KTOT
    int m = idx / KTOT;
    int k = idx - m * KTOT;
    float v = W[idx];
    __nv_bfloat16 hi = __float2bfloat16(v);
    __nv_bfloat16 lo = __float2bfloat16(v - __bfloat162float(hi));
    __nv_bfloat16* o = d_Wc + (size_t)m * K3;
    o[k] = hi; o[KTOT + k] = hi; o[2 * KTOT + k] = lo;
}

// ---------------- gather + bf16-split: Bc[u][k'] (t0=hi, t1=lo, t2=hi) ----------------
__global__ void gatherc_kernel(const float* __restrict__ x) {
    int idx = blockIdx.x * 256 + threadIdx.x;   // NU2*KTOT
    int u = idx / KTOT;
    int k = idx - u * KTOT;
    if (u >= d_Upad) return;
    int s = d_uniqPos[u];
    int ci = k / 9;
    int r  = k - ci * 9;
    int ky = r / 3;
    int kx = r - ky * 3;
    int y  = (s >> 7) + ky - 1;
    int xx = (s & 127) + kx - 1;
    float v = 0.0f;
    if (((unsigned)y < 128u) && ((unsigned)xx < 128u))
        v = x[ci * HW + y * GW + xx];
    __nv_bfloat16 hi = __float2bfloat16(v);
    __nv_bfloat16 lo = __float2bfloat16(v - __bfloat162float(hi));
    __nv_bfloat16* o = d_Bc + (size_t)u * K3;
    o[k] = hi; o[KTOT + k] = lo; o[2 * KTOT + k] = hi;
}

// ---------------- HMMA GEMM: d_hp[ks][u][m] = Wc @ Bc^T (bf16 mma.sync) ----------------
// grid (17, 4, KSPLIT), 256 threads (8 warps: 4 in M x 2 in N), CTA tile 128x64, BK=64.
__global__ void __launch_bounds__(256) gemm_hmma(void) {
    int n0 = blockIdx.x * 64;
    if (n0 >= d_Upad) return;                  // dedup early-exit
    int m0 = blockIdx.y * 128;
    int ks = blockIdx.z;
    int kq0 = ks * KQ;

    extern __shared__ __nv_bfloat16 sm[];
    // layout (halves): A0 [128*72], A1, B0 [64*72], B1
    const int AOFF0 = 0, AOFF1 = 128 * ASTRIDE;
    const int BOFF0 = 2 * 128 * ASTRIDE, BOFF1 = BOFF0 + 64 * ASTRIDE;
    uint32_t smBase = smem_u32(sm);

    int t = threadIdx.x;
    int wid = t >> 5, lane = t & 31;
    int wm = wid & 3, wn = wid >> 2;

    float d[2][4][4];
    #pragma unroll
    for (int i = 0; i < 2; i++)
        #pragma unroll
        for (int j = 0; j < 4; j++)
            #pragma unroll
            for (int e = 0; e < 4; e++) d[i][j][e] = 0.0f;

    // per-thread gmem load slots: A 4x uint4, B 2x uint4 per chunk
    int aRow[4], aC16[4], bRow[2], bC16[2];
    #pragma unroll
    for (int i = 0; i < 4; i++) { int u = i * 256 + t; aRow[i] = u >> 3; aC16[i] = u & 7; }
    #pragma unroll
    for (int i = 0; i < 2; i++) { int u = i * 256 + t; bRow[i] = u >> 3; bC16[i] = u & 7; }

    uint4 av[4], bv[2];
    #define LOADG(kc) do {                                                         \
        _Pragma("unroll")                                                          \
        for (int i = 0; i < 4; i++)                                                \
            av[i] = *(const uint4*)(d_Wc + (size_t)(m0 + aRow[i]) * K3 + kq0 + (kc) + aC16[i] * 8); \
        _Pragma("unroll")                                                          \
        for (int i = 0; i < 2; i++)                                                \
            bv[i] = *(const uint4*)(d_Bc + (size_t)(n0 + bRow[i]) * K3 + kq0 + (kc) + bC16[i] * 8); \
    } while (0)
    #define STORES(aoff, boff) do {                                                \
        _Pragma("unroll")                                                          \
        for (int i = 0; i < 4; i++)                                                \
            *(uint4*)(sm + (aoff) + aRow[i] * ASTRIDE + aC16[i] * 8) = av[i];      \
        _Pragma("unroll")                                                          \
        for (int i = 0; i < 2; i++)                                                \
            *(uint4*)(sm + (boff) + bRow[i] * ASTRIDE + bC16[i] * 8) = bv[i];      \
    } while (0)

    LOADG(0);
    STORES(AOFF0, BOFF0);
    __syncthreads();

    for (int ch = 0; ch < NCHUNK2; ch++) {
        int aoff = (ch & 1) ? AOFF1 : AOFF0;
        int boff = (ch & 1) ? BOFF1 : BOFF0;
        if (ch + 1 < NCHUNK2) LOADG((ch + 1) * BK);

        #pragma unroll
        for (int s = 0; s < 4; s++) {          // 4 k16 steps per BK=64
            int koff = s * 16;
            uint32_t a[2][4], b[4][2];
            #pragma unroll
            for (int tm = 0; tm < 2; tm++) {
                uint32_t addr = smBase + 2 * (uint32_t)(aoff +
                    (wm * 32 + tm * 16 + (lane & 15)) * ASTRIDE + koff + ((lane >> 4) << 3));
                asm volatile("ldmatrix.sync.aligned.m8n8.x4.shared.b16 {%0,%1,%2,%3}, [%4];"
                    : "=r"(a[tm][0]), "=r"(a[tm][1]), "=r"(a[tm][2]), "=r"(a[tm][3]) : "r"(addr));
            }
            #pragma unroll
            for (int tn = 0; tn < 4; tn++) {
                uint32_t addr = smBase + 2 * (uint32_t)(boff +
                    (wn * 32 + tn * 8 + (lane & 7)) * ASTRIDE + koff + (((lane >> 3) & 1) << 3));
                asm volatile("ldmatrix.sync.aligned.m8n8.x2.shared.b16 {%0,%1}, [%2];"
                    : "=r"(b[tn][0]), "=r"(b[tn][1]) : "r"(addr));
            }
            #pragma unroll
            for (int tm = 0; tm < 2; tm++)
                #pragma unroll
                for (int tn = 0; tn < 4; tn++)
                    asm volatile(
                        "mma.sync.aligned.m16n8k16.row.col.f32.bf16.bf16.f32 "
                        "{%0,%1,%2,%3}, {%4,%5,%6,%7}, {%8,%9}, {%0,%1,%2,%3};"
                        : "+f"(d[tm][tn][0]), "+f"(d[tm][tn][1]),
                          "+f"(d[tm][tn][2]), "+f"(d[tm][tn][3])
                        : "r"(a[tm][0]), "r"(a[tm][1]), "r"(a[tm][2]), "r"(a[tm][3]),
                          "r"(b[tn][0]), "r"(b[tn][1]));
        }
        __syncthreads();
        if (ch + 1 < NCHUNK2) {
            STORES((ch & 1) ? AOFF0 : AOFF1, (ch & 1) ? BOFF0 : BOFF1);
            __syncthreads();
        }
    }

    // epilogue: d_hp[ks][n][m]; lane g=lane>>2, tq=lane&3
    int g = lane >> 2, tq = lane & 3;
    float* hpBase = d_hp + (size_t)(ks * NU2) * CIN;
    #pragma unroll
    for (int tm = 0; tm < 2; tm++) {
        int rm = m0 + wm * 32 + tm * 16 + g;
        #pragma unroll
        for (int tn = 0; tn < 4; tn++) {
            int cn = n0 + wn * 32 + tn * 8 + tq * 2;
            hpBase[(size_t)cn * CIN + rm]           = d[tm][tn][0];
            hpBase[(size_t)(cn + 1) * CIN + rm]     = d[tm][tn][1];
            hpBase[(size_t)cn * CIN + rm + 8]       = d[tm][tn][2];
            hpBase[(size_t)(cn + 1) * CIN + rm + 8] = d[tm][tn][3];
        }
    }
}

// ---------------- per-column 1x1 conv dot (fused partial-reduce + bias + relu) ----------------
__global__ void coldot_kernel(const float* __restrict__ bw, const float* __restrict__ bb,
                              const float* __restrict__ sw, const float* __restrict__ sb,
                              const float* __restrict__ conv_b) {
    int col = blockIdx.x * 8 + (threadIdx.x >> 5);
    int lane = threadIdx.x & 31;
    int npos = d_nPos;
    int u;
    if (col < 512)      { int t = col >> 2;         u = (t < npos) ? 1 + col : 0; }
    else if (col < 768) { int t = (col - 512) >> 1; u = (t < npos) ? 1 + 4 * npos + (col - 512) : 0; }
    else                { int g = (col - 768) >> 1; u = (g < 256 - npos) ? 1 + 6 * npos + (col - 768) : 0; }
    if (u == 0) return;
    int meta = d_colMeta[col];
    const float* w;
    float b;
    if (meta < 36) { w = bw + meta * 512; b = bb[meta]; }
    else           { w = sw + (meta - 36) * 512; b = sb[meta - 36]; }
    const float4* wv = (const float4*)w;
    const float4* bias4 = (const float4*)conv_b;
    float s = 0.0f;
    for (int i = lane; i < 128; i += 32) {
        float4 a = bias4[i];
        #pragma unroll
        for (int ks = 0; ks < KSPLIT; ks++) {
            const float4* hp4 = (const float4*)(d_hp + (size_t)(ks * NU2 + u) * CIN);
            float4 hv = hp4[i];
            a.x += hv.x; a.y += hv.y; a.z += hv.z; a.w += hv.w;
        }
        a.x = fmaxf(a.x, 0.0f); a.y = fmaxf(a.y, 0.0f);
        a.z = fmaxf(a.z, 0.0f); a.w = fmaxf(a.w, 0.0f);
        float4 ww = wv[i];
        s += a.x * ww.x + a.y * ww.y + a.z * ww.z + a.w * ww.w;
    }
    #pragma unroll
    for (int o = 16; o > 0; o >>= 1) s += __shfl_xor_sync(0xFFFFFFFFu, s, o);
    if (lane == 0) d_val[col] = fmaxf(s + b, 0.0f);
}

// ---------------- loss ----------------
__global__ void loss_kernel(const float* __restrict__ target, float* __restrict__ out) {
    __shared__ float rce[256], rsl[256], rvc[256];
    int t = threadIdx.x;
    float ce = 0.0f, sl = 0.0f, vc = 0.0f;
    if (t < 128 && d_posValid[t]) {
        float s0 = d_val[512 + 2 * t], s1 = d_val[512 + 2 * t + 1];
        float m = fmaxf(s0, s1);
        float lse = m + logf(expf(s0 - m) + expf(s1 - m));
        ce += lse - s0;
        vc += 1.0f;
        int p = d_posIdx[t];
        int k = p % 9;
        int q = p / 9;
        int wq = q & 127;
        int hq = q >> 7;
        float ax1 = hq * STEP, ay1 = wq * STEP;
        float aw = d_whw[k], ah = d_whh[k];
        float acx = ax1 + aw * 0.5f, acy = ay1 + ah * 0.5f;
        float4 tb = ((const float4*)target)[d_tgtIdx[p]];
        float bw_ = tb.z - tb.x, bh_ = tb.w - tb.y;
        float bcx = tb.x + bw_ * 0.5f, bcy = tb.y + bh_ * 0.5f;
        float tr[4] = {(bcx - acx) / aw, (bcy - acy) / ah,
                       logf(bw_ / aw), logf(bh_ / ah)};
        #pragma unroll
        for (int e = 0; e < 4; e++) {
            float dd = d_val[4 * t + e] - tr[e];
            float ad = fabsf(dd);
            sl += (ad < 1.0f) ? 0.5f * dd * dd : (ad - 0.5f);
        }
    }
    if (t < 256 && d_negValid[t]) {
        float s0 = d_val[768 + 2 * t], s1 = d_val[768 + 2 * t + 1];
        float m = fmaxf(s0, s1);
        float lse = m + logf(expf(s0 - m) + expf(s1 - m));
        ce += lse - s1;
        vc += 1.0f;
    }
    rce[t] = ce; rsl[t] = sl; rvc[t] = vc;
    __syncthreads();
    for (int s2 = 128; s2 > 0; s2 >>= 1) {
        if (t < s2) { rce[t] += rce[t + s2]; rsl[t] += rsl[t + s2]; rvc[t] += rvc[t + s2]; }
        __syncthreads();
    }
    if (t == 0) {
        float np = (float)d_nPos;
        float score_loss = rce[0] / fmaxf(rvc[0], 1.0f);
        float reg_loss = rsl[0] / fmaxf(np * 4.0f, 1.0f);
        out[0] = score_loss + 10.0f * reg_loss;
    }
}

// ---------------- launch ----------------
extern "C" void kernel_launch(void* const* d_in, const int* in_sizes, int n_in,
                              void* d_out, int out_size) {
    const float* x       = (const float*)d_in[0];
    const float* target  = (const float*)d_in[1];
    const float* conv_w  = (const float*)d_in[2];
    const float* conv_b  = (const float*)d_in[3];
    const float* bbox_w  = (const float*)d_in[4];
    const float* bbox_b  = (const float*)d_in[5];
    const float* score_w = (const float*)d_in[6];
    const float* score_b = (const float*)d_in[7];
    float* out = (float*)d_out;

    // smem: (128+64)*72*2 halves * 2 bytes = 55296 B
    const int DSMEM = (2 * 128 * ASTRIDE + 2 * 64 * ASTRIDE) * 2;
    cudaFuncSetAttribute(gemm_hmma, cudaFuncAttributeMaxDynamicSharedMemorySize, DSMEM);

    iou_kernel<<<NBLK, 256>>>(target);
    selection_kernel<<<1, 1024>>>();
    wconv_kernel<<<(CIN * KTOT) / 256, 256>>>(conv_w);
    gatherc_kernel<<<(NU2 * KTOT) / 256, 256>>>(x);
    gemm_hmma<<<dim3(NU2 / 64, CIN / 128, KSPLIT), 256, DSMEM>>>();
    coldot_kernel<<<NCOL / 8, 256>>>(bbox_w, bbox_b, score_w, score_b, conv_b);
    loss_kernel<<<1, 256>>>(target, out);
}

// round 12
// speedup vs baseline: 1.5411x; 1.0085x over previous
#include <cuda_runtime.h>
#include <cuda_bf16.h>
#include <math.h>
#include <stdint.h>

#define A_TOT 147456      // 128*128*9 anchors
#define HW    16384
#define GW    128
#define CIN   512
#define KTOT  4608        // 512*9
#define K3    13824       // 3*KTOT (bf16-split expanded K)
#define KSPLIT 8
#define KQ    1728        // K3/KSPLIT
#define BK    64
#define NCH   27          // KQ/BK
#define NCOL  1280
#define NU2   1088        // max unique columns padded (17 tiles of 64)
#define NBLK  576
#define STEP  (2048.0f/127.0f)
#define ASTRIDE 72        // smem row stride in halves (64 + 8 pad)
#define STG   ((128 + 64) * ASTRIDE)   // halves per pipeline stage
#define WBLK  9216        // wconv blocks: CIN*KTOT/256
#define GBLK  19584       // gather blocks: NU2*KTOT/256

__constant__ float d_whw[9] = {128.0f, 181.01933598375618f, 90.50966799187809f,
                               256.0f, 362.03867196751236f, 181.01933598375618f,
                               512.0f, 724.0773439350247f, 362.03867196751236f};
__constant__ float d_whh[9] = {128.0f, 90.50966799187809f, 181.01933598375618f,
                               256.0f, 181.01933598375618f, 362.03867196751236f,
                               512.0f, 362.03867196751236f, 724.0773439350247f};

// ---------------- static device scratch ----------------
__device__ float d_maxIou[A_TOT];
__device__ int   d_tgtIdx[A_TOT];
__device__ int   d_posIdx[128];
__device__ int   d_posValid[128];
__device__ int   d_negValid[256];
__device__ int   d_nPos;
__device__ int   d_Upad;
__device__ int   d_colPos[NCOL];
__device__ int   d_colMeta[NCOL];
__device__ int   d_uniqPos[NU2];
__device__ __align__(16) __nv_bfloat16 d_Wc[(size_t)CIN * K3];   // weights split [m][k']
__device__ __align__(16) __nv_bfloat16 d_Bc[(size_t)NU2 * K3];   // patches split [u][k']
__device__ float d_hp[KSPLIT * NU2 * CIN];                        // partials [ks][u][m]
__device__ float d_val[NCOL];

__device__ __forceinline__ uint32_t smem_u32(const void* p) {
    uint32_t a;
    asm("{ .reg .u64 t; cvta.to.shared.u64 t, %1; cvt.u32.u64 %0, t; }" : "=r"(a) : "l"(p));
    return a;
}

// ---------------- phase A: IoU matching ----------------
__global__ void iou_kernel(const float* __restrict__ target) {
    __shared__ float4 tg[64];
    int t = threadIdx.x;
    if (t < 64) tg[t] = ((const float4*)target)[t];
    __syncthreads();
    int a = blockIdx.x * 256 + t;
    int k = a % 9;
    int q = a / 9;
    int wq = q & 127;
    int hq = q >> 7;
    float x1 = hq * STEP;
    float y1 = wq * STEP;
    float x2 = x1 + d_whw[k];
    float y2 = y1 + d_whh[k];
    float areaA = (x2 - x1) * (y2 - y1);
    float best = -1.0f;
    int bi = 0;
    #pragma unroll 4
    for (int i = 0; i < 64; i++) {
        float4 b = tg[i];
        float lx = fmaxf(b.x, x1), ly = fmaxf(b.y, y1);
        float rx = fminf(b.z, x2), ry = fminf(b.w, y2);
        float iw = fmaxf(rx - lx, 0.0f), ih = fmaxf(ry - ly, 0.0f);
        float inter = iw * ih;
        float at = (b.z - b.x) * (b.w - b.y);
        float iou = inter / (at + areaA - inter);
        if (iou > best) { best = iou; bi = i; }   // first-max == jnp.argmax
    }
    d_maxIou[a] = best;
    d_tgtIdx[a] = bi;
}

// ---------------- fallback sort (1024 threads) ----------------
__device__ __forceinline__ void bitonic2048(unsigned long long* s) {
    int t = threadIdx.x;
    for (int k = 2; k <= 2048; k <<= 1) {
        for (int j = k >> 1; j > 0; j >>= 1) {
            __syncthreads();
            #pragma unroll
            for (int base = 0; base < 2048; base += 1024) {
                int i = base + t;
                int ixj = i ^ j;
                if (ixj > i) {
                    unsigned long long va = s[i], vb = s[ixj];
                    bool sw = ((i & k) == 0) ? (va < vb) : (va > vb);
                    if (sw) { s[i] = vb; s[ixj] = va; }
                }
            }
        }
    }
    __syncthreads();
}

// ---------------- phase B: one-kernel selection + column tables ----------------
__global__ void selection_kernel() {   // 1 block x 1024
    __shared__ unsigned long long pKeys[2048];
    __shared__ int zIdx[256];
    __shared__ int wz[32], wp[32];
    __shared__ int zTot, pTot, zBase, pBase;
    int t = threadIdx.x, lane = t & 31, w = t >> 5;
    if (t == 0) { zTot = 0; pTot = 0; }
    __syncthreads();
    for (int it = 0; it < A_TOT / 1024; it++) {
        int a = it * 1024 + t;
        float best = d_maxIou[a];
        bool zf = (zTot < 256);
        bool z = zf && (best < 0.3f) && ((1.0f - best) == 1.0f);  // exact ref tie-class
        bool p = (best > 0.7f);
        unsigned zb = __ballot_sync(0xFFFFFFFFu, z);
        unsigned pb = __ballot_sync(0xFFFFFFFFu, p);
        if (lane == 0) { wz[w] = __popc(zb); wp[w] = __popc(pb); }
        __syncthreads();
        if (w == 0) {
            int vz = wz[lane], vp = wp[lane];
            int sz = vz, sp = vp;
            #pragma unroll
            for (int o = 1; o < 32; o <<= 1) {
                int xz = __shfl_up_sync(0xFFFFFFFFu, sz, o);
                int xp = __shfl_up_sync(0xFFFFFFFFu, sp, o);
                if (lane >= o) { sz += xz; sp += xp; }
            }
            wz[lane] = sz - vz;
            wp[lane] = sp - vp;
            if (lane == 31) {
                zBase = zTot; pBase = pTot;
                zTot = zTot + sz; pTot = pTot + sp;
            }
        }
        __syncthreads();
        if (z) {
            int r = zBase + wz[w] + __popc(zb & ((1u << lane) - 1));
            if (r < 256) zIdx[r] = a;
        }
        if (p) {
            int r = pBase + wp[w] + __popc(pb & ((1u << lane) - 1));
            if (r < 2048)
                pKeys[r] = (((unsigned long long)__float_as_uint(best) << 32) |
                            (0xFFFFFFFFu - (unsigned)a));
        }
        __syncthreads();
    }
    int cnt = pTot;
    int npos = cnt < 128 ? cnt : 128;
    int K = 256 - npos;
    if (t == 0) {
        d_nPos = npos;
        int U = 513 + 4 * npos;
        d_Upad = (U + 63) & ~63;
    }
    if (cnt > 128) {
        int stored = cnt < 2048 ? cnt : 2048;
        for (int i = t; i < 2048; i += 1024)
            if (i >= stored) pKeys[i] = 0ULL;
        __syncthreads();
        bitonic2048(pKeys);
    }
    __syncthreads();
    if (t < 128) {
        int valid = (t < npos);
        d_posValid[t] = valid;
        if (valid) {
            int p = (int)(0xFFFFFFFFu - (unsigned)(pKeys[t] & 0xFFFFFFFFULL));
            d_posIdx[t] = p;
            int sb = (4 * p) & 16383;
            int ssc = (2 * p) & 16383;
            int cb = p >> 12;
            int cs = 36 + (p >> 13);
            #pragma unroll
            for (int e = 0; e < 4; e++) {
                d_colPos[4 * t + e] = sb + e;
                d_colMeta[4 * t + e] = cb;
            }
            #pragma unroll
            for (int e = 0; e < 2; e++) {
                d_colPos[512 + 2 * t + e] = ssc + e;
                d_colMeta[512 + 2 * t + e] = cs;
            }
        }
    }
    if (t < 256) {
        d_negValid[t] = (t < K);
        if (t < K) {
            int a = zIdx[t];
            int ss = (2 * a) & 16383;
            int cs = 36 + (a >> 13);
            d_colPos[768 + 2 * t] = ss;         d_colMeta[768 + 2 * t] = cs;
            d_colPos[768 + 2 * t + 1] = ss + 1; d_colMeta[768 + 2 * t + 1] = cs;
        }
    }
    __syncthreads();
    for (int u = t; u < NU2; u += 1024) {
        int pos = 0;
        if (u >= 1) {
            int v = u - 1;
            if (v < 4 * npos)              pos = d_colPos[v];
            else if (v < 6 * npos)         pos = d_colPos[512 + (v - 4 * npos)];
            else if (v < 6 * npos + 2 * K) pos = d_colPos[768 + (v - 6 * npos)];
        }
        d_uniqPos[u] = pos;
    }
}

// ---------------- fused prep: weight bf16-split + gather bf16-split ----------------
__global__ void prep_kernel(const float* __restrict__ W, const float* __restrict__ x) {
    if (blockIdx.x < WBLK) {
        int idx = blockIdx.x * 256 + threadIdx.x;   // CIN*KTOT
        int m = idx / KTOT;
        int k = idx - m * KTOT;
        float v = W[idx];
        __nv_bfloat16 hi = __float2bfloat16(v);
        __nv_bfloat16 lo = __float2bfloat16(v - __bfloat162float(hi));
        __nv_bfloat16* o = d_Wc + (size_t)m * K3;
        o[k] = hi; o[KTOT + k] = hi; o[2 * KTOT + k] = lo;
    } else {
        int idx = (blockIdx.x - WBLK) * 256 + threadIdx.x;   // NU2*KTOT
        int u = idx / KTOT;
        int k = idx - u * KTOT;
        if (u >= d_Upad) return;
        int s = d_uniqPos[u];
        int ci = k / 9;
        int r  = k - ci * 9;
        int ky = r / 3;
        int kx = r - ky * 3;
        int y  = (s >> 7) + ky - 1;
        int xx = (s & 127) + kx - 1;
        float v = 0.0f;
        if (((unsigned)y < 128u) && ((unsigned)xx < 128u))
            v = x[ci * HW + y * GW + xx];
        __nv_bfloat16 hi = __float2bfloat16(v);
        __nv_bfloat16 lo = __float2bfloat16(v - __bfloat162float(hi));
        __nv_bfloat16* o = d_Bc + (size_t)u * K3;
        o[k] = hi; o[KTOT + k] = lo; o[2 * KTOT + k] = hi;
    }
}

// ---------------- HMMA GEMM, cp.async 3-stage: d_hp[ks][u][m] = Wc @ Bc^T ----------------
// grid (17, 4, KSPLIT), 256 threads (8 warps: 4M x 2N), CTA tile 128x64, BK=64.
__global__ void __launch_bounds__(256) gemm_hmma(void) {
    int n0 = blockIdx.x * 64;
    if (n0 >= d_Upad) return;                  // dedup early-exit
    int m0 = blockIdx.y * 128;
    int ks = blockIdx.z;
    int kq0 = ks * KQ;

    extern __shared__ __nv_bfloat16 sm[];
    uint32_t smBase = smem_u32(sm);

    int t = threadIdx.x;
    int wid = t >> 5, lane = t & 31;
    int wm = wid & 3, wn = wid >> 2;

    float acc[2][4][4];
    #pragma unroll
    for (int i = 0; i < 2; i++)
        #pragma unroll
        for (int j = 0; j < 4; j++)
            #pragma unroll
            for (int e = 0; e < 4; e++) acc[i][j][e] = 0.0f;

    // per-thread cp.async slots: A 4x16B, B 2x16B per chunk
    const __nv_bfloat16* aG[4];
    const __nv_bfloat16* bG[2];
    uint32_t aS[4], bS[2];
    #pragma unroll
    for (int i = 0; i < 4; i++) {
        int u = i * 256 + t;
        int row = u >> 3, c16 = u & 7;
        aG[i] = d_Wc + (size_t)(m0 + row) * K3 + kq0 + c16 * 8;
        aS[i] = smBase + 2 * (uint32_t)(row * ASTRIDE + c16 * 8);
    }
    #pragma unroll
    for (int i = 0; i < 2; i++) {
        int u = i * 256 + t;
        int row = u >> 3, c16 = u & 7;
        bG[i] = d_Bc + (size_t)(n0 + row) * K3 + kq0 + c16 * 8;
        bS[i] = smBase + 2 * (uint32_t)(128 * ASTRIDE + row * ASTRIDE + c16 * 8);
    }

    #define ISSUE(ch) do {                                                     \
        uint32_t so = 2u * (uint32_t)(((ch) % 3) * STG);                       \
        int ko = (ch) * BK;                                                    \
        _Pragma("unroll")                                                      \
        for (int i = 0; i < 4; i++)                                            \
            asm volatile("cp.async.cg.shared.global [%0], [%1], 16;"           \
                :: "r"(aS[i] + so), "l"(aG[i] + ko) : "memory");               \
        _Pragma("unroll")                                                      \
        for (int i = 0; i < 2; i++)                                            \
            asm volatile("cp.async.cg.shared.global [%0], [%1], 16;"           \
                :: "r"(bS[i] + so), "l"(bG[i] + ko) : "memory");               \
        asm volatile("cp.async.commit_group;" ::: "memory");                   \
    } while (0)

    ISSUE(0);
    ISSUE(1);

    for (int ch = 0; ch < NCH; ch++) {
        if (ch + 1 < NCH) asm volatile("cp.async.wait_group 1;" ::: "memory");
        else              asm volatile("cp.async.wait_group 0;" ::: "memory");
        __syncthreads();
        if (ch + 2 < NCH) ISSUE(ch + 2);

        uint32_t so = 2u * (uint32_t)((ch % 3) * STG);
        #pragma unroll
        for (int s = 0; s < 4; s++) {          // 4 k16 steps per BK=64
            int koff = s * 16;
            uint32_t a[2][4], b[2][4];
            #pragma unroll
            for (int tm = 0; tm < 2; tm++) {
                uint32_t addr = smBase + so + 2 * (uint32_t)(
                    (wm * 32 + tm * 16 + (lane & 15)) * ASTRIDE + koff + ((lane >> 4) << 3));
                asm volatile("ldmatrix.sync.aligned.m8n8.x4.shared.b16 {%0,%1,%2,%3}, [%4];"
                    : "=r"(a[tm][0]), "=r"(a[tm][1]), "=r"(a[tm][2]), "=r"(a[tm][3]) : "r"(addr));
            }
            #pragma unroll
            for (int p = 0; p < 2; p++) {      // each x4 feeds 2 n-subtiles
                int g = lane >> 3;
                int row = wn * 32 + p * 16 + ((g >> 1) << 3) + (lane & 7);
                int kadd = (g & 1) << 3;
                uint32_t addr = smBase + so + 2 * (uint32_t)(
                    128 * ASTRIDE + row * ASTRIDE + koff + kadd);
                asm volatile("ldmatrix.sync.aligned.m8n8.x4.shared.b16 {%0,%1,%2,%3}, [%4];"
                    : "=r"(b[p][0]), "=r"(b[p][1]), "=r"(b[p][2]), "=r"(b[p][3]) : "r"(addr));
            }
            #pragma unroll
            for (int tm = 0; tm < 2; tm++)
                #pragma unroll
                for (int tn = 0; tn < 4; tn++) {
                    int p = tn >> 1, h = (tn & 1) << 1;
                    asm volatile(
                        "mma.sync.aligned.m16n8k16.row.col.f32.bf16.bf16.f32 "
                        "{%0,%1,%2,%3}, {%4,%5,%6,%7}, {%8,%9}, {%0,%1,%2,%3};"
                        : "+f"(acc[tm][tn][0]), "+f"(acc[tm][tn][1]),
                          "+f"(acc[tm][tn][2]), "+f"(acc[tm][tn][3])
                        : "r"(a[tm][0]), "r"(a[tm][1]), "r"(a[tm][2]), "r"(a[tm][3]),
                          "r"(b[p][h]), "r"(b[p][h + 1]));
                }
        }
        __syncthreads();
    }

    // epilogue: d_hp[ks][n][m]; lane g=lane>>2, tq=lane&3
    int g = lane >> 2, tq = lane & 3;
    float* hpBase = d_hp + (size_t)(ks * NU2) * CIN;
    #pragma unroll
    for (int tm = 0; tm < 2; tm++) {
        int rm = m0 + wm * 32 + tm * 16 + g;
        #pragma unroll
        for (int tn = 0; tn < 4; tn++) {
            int cn = n0 + wn * 32 + tn * 8 + tq * 2;
            hpBase[(size_t)cn * CIN + rm]           = acc[tm][tn][0];
            hpBase[(size_t)(cn + 1) * CIN + rm]     = acc[tm][tn][1];
            hpBase[(size_t)cn * CIN + rm + 8]       = acc[tm][tn][2];
            hpBase[(size_t)(cn + 1) * CIN + rm + 8] = acc[tm][tn][3];
        }
    }
}

// ---------------- per-column 1x1 conv dot (fused partial-reduce + bias + relu) ----------------
__global__ void coldot_kernel(const float* __restrict__ bw, const float* __restrict__ bb,
                              const float* __restrict__ sw, const float* __restrict__ sb,
                              const float* __restrict__ conv_b) {
    int col = blockIdx.x * 8 + (threadIdx.x >> 5);
    int lane = threadIdx.x & 31;
    int npos = d_nPos;
    int u;
    if (col < 512)      { int t = col >> 2;         u = (t < npos) ? 1 + col : 0; }
    else if (col < 768) { int t = (col - 512) >> 1; u = (t < npos) ? 1 + 4 * npos + (col - 512) : 0; }
    else                { int g = (col - 768) >> 1; u = (g < 256 - npos) ? 1 + 6 * npos + (col - 768) : 0; }
    if (u == 0) return;
    int meta = d_colMeta[col];
    const float* w;
    float b;
    if (meta < 36) { w = bw + meta * 512; b = bb[meta]; }
    else           { w = sw + (meta - 36) * 512; b = sb[meta - 36]; }
    const float4* wv = (const float4*)w;
    const float4* bias4 = (const float4*)conv_b;
    float s = 0.0f;
    for (int i = lane; i < 128; i += 32) {
        float4 a = bias4[i];
        #pragma unroll
        for (int ks = 0; ks < KSPLIT; ks++) {
            const float4* hp4 = (const float4*)(d_hp + (size_t)(ks * NU2 + u) * CIN);
            float4 hv = hp4[i];
            a.x += hv.x; a.y += hv.y; a.z += hv.z; a.w += hv.w;
        }
        a.x = fmaxf(a.x, 0.0f); a.y = fmaxf(a.y, 0.0f);
        a.z = fmaxf(a.z, 0.0f); a.w = fmaxf(a.w, 0.0f);
        float4 ww = wv[i];
        s += a.x * ww.x + a.y * ww.y + a.z * ww.z + a.w * ww.w;
    }
    #pragma unroll
    for (int o = 16; o > 0; o >>= 1) s += __shfl_xor_sync(0xFFFFFFFFu, s, o);
    if (lane == 0) d_val[col] = fmaxf(s + b, 0.0f);
}

// ---------------- loss ----------------
__global__ void loss_kernel(const float* __restrict__ target, float* __restrict__ out) {
    __shared__ float rce[256], rsl[256], rvc[256];
    int t = threadIdx.x;
    float ce = 0.0f, sl = 0.0f, vc = 0.0f;
    if (t < 128 && d_posValid[t]) {
        float s0 = d_val[512 + 2 * t], s1 = d_val[512 + 2 * t + 1];
        float m = fmaxf(s0, s1);
        float lse = m + logf(expf(s0 - m) + expf(s1 - m));
        ce += lse - s0;
        vc += 1.0f;
        int p = d_posIdx[t];
        int k = p % 9;
        int q = p / 9;
        int wq = q & 127;
        int hq = q >> 7;
        float ax1 = hq * STEP, ay1 = wq * STEP;
        float aw = d_whw[k], ah = d_whh[k];
        float acx = ax1 + aw * 0.5f, acy = ay1 + ah * 0.5f;
        float4 tb = ((const float4*)target)[d_tgtIdx[p]];
        float bw_ = tb.z - tb.x, bh_ = tb.w - tb.y;
        float bcx = tb.x + bw_ * 0.5f, bcy = tb.y + bh_ * 0.5f;
        float tr[4] = {(bcx - acx) / aw, (bcy - acy) / ah,
                       logf(bw_ / aw), logf(bh_ / ah)};
        #pragma unroll
        for (int e = 0; e < 4; e++) {
            float dd = d_val[4 * t + e] - tr[e];
            float ad = fabsf(dd);
            sl += (ad < 1.0f) ? 0.5f * dd * dd : (ad - 0.5f);
        }
    }
    if (t < 256 && d_negValid[t]) {
        float s0 = d_val[768 + 2 * t], s1 = d_val[768 + 2 * t + 1];
        float m = fmaxf(s0, s1);
        float lse = m + logf(expf(s0 - m) + expf(s1 - m));
        ce += lse - s1;
        vc += 1.0f;
    }
    rce[t] = ce; rsl[t] = sl; rvc[t] = vc;
    __syncthreads();
    for (int s2 = 128; s2 > 0; s2 >>= 1) {
        if (t < s2) { rce[t] += rce[t + s2]; rsl[t] += rsl[t + s2]; rvc[t] += rvc[t + s2]; }
        __syncthreads();
    }
    if (t == 0) {
        float np = (float)d_nPos;
        float score_loss = rce[0] / fmaxf(rvc[0], 1.0f);
        float reg_loss = rsl[0] / fmaxf(np * 4.0f, 1.0f);
        out[0] = score_loss + 10.0f * reg_loss;
    }
}

// ---------------- launch ----------------
extern "C" void kernel_launch(void* const* d_in, const int* in_sizes, int n_in,
                              void* d_out, int out_size) {
    const float* x       = (const float*)d_in[0];
    const float* target  = (const float*)d_in[1];
    const float* conv_w  = (const float*)d_in[2];
    const float* conv_b  = (const float*)d_in[3];
    const float* bbox_w  = (const float*)d_in[4];
    const float* bbox_b  = (const float*)d_in[5];
    const float* score_w = (const float*)d_in[6];
    const float* score_b = (const float*)d_in[7];
    float* out = (float*)d_out;

    // smem: 3 stages x (128+64)*72 halves * 2B = 82944 B
    const int DSMEM = 3 * STG * 2;
    cudaFuncSetAttribute(gemm_hmma, cudaFuncAttributeMaxDynamicSharedMemorySize, DSMEM);

    iou_kernel<<<NBLK, 256>>>(target);
    selection_kernel<<<1, 1024>>>();
    prep_kernel<<<WBLK + GBLK, 256>>>(conv_w, x);
    gemm_hmma<<<dim3(NU2 / 64, CIN / 128, KSPLIT), 256, DSMEM>>>();
    coldot_kernel<<<NCOL / 8, 256>>>(bbox_w, bbox_b, score_w, score_b, conv_b);
    loss_kernel<<<1, 256>>>(target, out);
}

// round 13
// speedup vs baseline: 1.8830x; 1.2219x over previous
#include <cuda_runtime.h>
#include <cuda_bf16.h>
#include <math.h>
#include <stdint.h>

#define A_TOT 147456      // 128*128*9 anchors
#define HW    16384
#define GW    128
#define CIN   512
#define KTOT  4608        // 512*9
#define K3    13824       // 3*KTOT (bf16-split expanded K)
#define KSPLIT 8
#define KQ    1728        // K3/KSPLIT
#define BK    64
#define NCH   27          // KQ/BK
#define NCOL  1280
#define NU2   1088        // max unique columns padded (17 tiles of 64)
#define NBLK  576
#define STEP  (2048.0f/127.0f)
#define ASTRIDE 72        // smem row stride in halves (64 + 8 pad)
#define STG   ((128 + 64) * ASTRIDE)   // halves per pipeline stage
#define WBLK  9216        // wconv blocks: CIN*KTOT/256
#define GBLK  19584       // gather blocks: NU2*KTOT/256
#define WREG  4608        // anchors per warp in selection (A_TOT/32)
#define WROWS 144         // rows of 32 per warp region

__constant__ float d_whw[9] = {128.0f, 181.01933598375618f, 90.50966799187809f,
                               256.0f, 362.03867196751236f, 181.01933598375618f,
                               512.0f, 724.0773439350247f, 362.03867196751236f};
__constant__ float d_whh[9] = {128.0f, 90.50966799187809f, 181.01933598375618f,
                               256.0f, 181.01933598375618f, 362.03867196751236f,
                               512.0f, 362.03867196751236f, 724.0773439350247f};

// ---------------- static device scratch ----------------
__device__ float d_maxIou[A_TOT];
__device__ int   d_tgtIdx[A_TOT];
__device__ int   d_posIdx[128];
__device__ int   d_posValid[128];
__device__ int   d_negValid[256];
__device__ int   d_nPos;
__device__ int   d_Upad;
__device__ int   d_colPos[NCOL];
__device__ int   d_colMeta[NCOL];
__device__ int   d_uniqPos[NU2];
__device__ __align__(16) __nv_bfloat16 d_Wc[(size_t)CIN * K3];   // weights split [m][k']
__device__ __align__(16) __nv_bfloat16 d_Bc[(size_t)NU2 * K3];   // patches split [u][k']
__device__ float d_hp[KSPLIT * NU2 * CIN];                        // partials [ks][u][m]
__device__ float d_val[NCOL];

__device__ __forceinline__ uint32_t smem_u32(const void* p) {
    uint32_t a;
    asm("{ .reg .u64 t; cvta.to.shared.u64 t, %1; cvt.u32.u64 %0, t; }" : "=r"(a) : "l"(p));
    return a;
}

// ---------------- phase A: IoU matching ----------------
__global__ void iou_kernel(const float* __restrict__ target) {
    __shared__ float4 tg[64];
    int t = threadIdx.x;
    if (t < 64) tg[t] = ((const float4*)target)[t];
    __syncthreads();
    int a = blockIdx.x * 256 + t;
    int k = a % 9;
    int q = a / 9;
    int wq = q & 127;
    int hq = q >> 7;
    float x1 = hq * STEP;
    float y1 = wq * STEP;
    float x2 = x1 + d_whw[k];
    float y2 = y1 + d_whh[k];
    float areaA = (x2 - x1) * (y2 - y1);
    float best = -1.0f;
    int bi = 0;
    #pragma unroll 4
    for (int i = 0; i < 64; i++) {
        float4 b = tg[i];
        float lx = fmaxf(b.x, x1), ly = fmaxf(b.y, y1);
        float rx = fminf(b.z, x2), ry = fminf(b.w, y2);
        float iw = fmaxf(rx - lx, 0.0f), ih = fmaxf(ry - ly, 0.0f);
        float inter = iw * ih;
        float at = (b.z - b.x) * (b.w - b.y);
        float iou = inter / (at + areaA - inter);
        if (iou > best) { best = iou; bi = i; }   // first-max == jnp.argmax
    }
    d_maxIou[a] = best;
    d_tgtIdx[a] = bi;
}

// ---------------- fallback sort (1024 threads) ----------------
__device__ __forceinline__ void bitonic2048(unsigned long long* s) {
    int t = threadIdx.x;
    for (int k = 2; k <= 2048; k <<= 1) {
        for (int j = k >> 1; j > 0; j >>= 1) {
            __syncthreads();
            #pragma unroll
            for (int base = 0; base < 2048; base += 1024) {
                int i = base + t;
                int ixj = i ^ j;
                if (ixj > i) {
                    unsigned long long va = s[i], vb = s[ixj];
                    bool sw = ((i & k) == 0) ? (va < vb) : (va > vb);
                    if (sw) { s[i] = vb; s[ixj] = va; }
                }
            }
        }
    }
    __syncthreads();
}

// ---------------- phase B: warp-parallel two-pass selection + column tables ----------------
__global__ void selection_kernel() {   // 1 block x 1024
    __shared__ unsigned long long pKeys[2048];
    __shared__ int zIdx[256];
    __shared__ int warpZ[32], warpP[32];
    __shared__ int zExS[32], pExS[32];
    __shared__ int pTotS;
    int t = threadIdx.x, lane = t & 31, w = t >> 5;
    unsigned lmLT = (1u << lane) - 1u;
    int wbase = w * WREG;

    // pass 1: per-warp class counts (coalesced rows of 32)
    int nzW = 0, npW = 0;
    #pragma unroll 4
    for (int i = 0; i < WROWS; i++) {
        float v = d_maxIou[wbase + i * 32 + lane];
        bool z = (v < 0.3f) && ((1.0f - v) == 1.0f);   // exact ref tie-class
        bool p = (v > 0.7f);
        nzW += __popc(__ballot_sync(0xFFFFFFFFu, z));
        npW += __popc(__ballot_sync(0xFFFFFFFFu, p));
    }
    if (lane == 0) { warpZ[w] = nzW; warpP[w] = npW; }
    __syncthreads();
    // exclusive scan over 32 warp totals (warp 0)
    if (w == 0) {
        int vz = warpZ[lane], vp = warpP[lane];
        int sz = vz, sp = vp;
        #pragma unroll
        for (int o = 1; o < 32; o <<= 1) {
            int xz = __shfl_up_sync(0xFFFFFFFFu, sz, o);
            int xp = __shfl_up_sync(0xFFFFFFFFu, sp, o);
            if (lane >= o) { sz += xz; sp += xp; }
        }
        zExS[lane] = sz - vz;
        pExS[lane] = sp - vp;
        if (lane == 31) pTotS = sp;
    }
    __syncthreads();

    // pass 2: replay with running bases; exact index-order ranks
    {
        int zr = zExS[w], pr = pExS[w];
        if (zr < 256 || pr < 2048) {
            for (int i = 0; i < WROWS; i++) {
                int a = wbase + i * 32 + lane;
                float v = d_maxIou[a];
                bool z = (v < 0.3f) && ((1.0f - v) == 1.0f);
                bool p = (v > 0.7f);
                unsigned bz = __ballot_sync(0xFFFFFFFFu, z);
                unsigned bp = __ballot_sync(0xFFFFFFFFu, p);
                if (z) {
                    int r = zr + __popc(bz & lmLT);
                    if (r < 256) zIdx[r] = a;
                }
                if (p) {
                    int r = pr + __popc(bp & lmLT);
                    if (r < 2048)
                        pKeys[r] = (((unsigned long long)__float_as_uint(v) << 32) |
                                    (0xFFFFFFFFu - (unsigned)a));
                }
                zr += __popc(bz);
                pr += __popc(bp);
                if (zr >= 256 && pr >= 2048) break;
            }
        }
    }
    __syncthreads();

    int cnt = pTotS;
    int npos = cnt < 128 ? cnt : 128;
    int K = 256 - npos;
    if (t == 0) {
        d_nPos = npos;
        int U = 513 + 4 * npos;
        d_Upad = (U + 63) & ~63;
    }
    if (cnt > 128) {
        // rare fallback: exact top-128 by (iou desc, index asc)
        int stored = cnt < 2048 ? cnt : 2048;
        for (int i = t; i < 2048; i += 1024)
            if (i >= stored) pKeys[i] = 0ULL;
        __syncthreads();
        bitonic2048(pKeys);
    }
    __syncthreads();
    if (t < 128) {
        int valid = (t < npos);
        d_posValid[t] = valid;
        if (valid) {
            int p = (int)(0xFFFFFFFFu - (unsigned)(pKeys[t] & 0xFFFFFFFFULL));
            d_posIdx[t] = p;
            int sb = (4 * p) & 16383;
            int ssc = (2 * p) & 16383;
            int cb = p >> 12;
            int cs = 36 + (p >> 13);
            #pragma unroll
            for (int e = 0; e < 4; e++) {
                d_colPos[4 * t + e] = sb + e;
                d_colMeta[4 * t + e] = cb;
            }
            #pragma unroll
            for (int e = 0; e < 2; e++) {
                d_colPos[512 + 2 * t + e] = ssc + e;
                d_colMeta[512 + 2 * t + e] = cs;
            }
        }
    }
    if (t < 256) {
        d_negValid[t] = (t < K);
        if (t < K) {
            int a = zIdx[t];
            int ss = (2 * a) & 16383;
            int cs = 36 + (a >> 13);
            d_colPos[768 + 2 * t] = ss;         d_colMeta[768 + 2 * t] = cs;
            d_colPos[768 + 2 * t + 1] = ss + 1; d_colMeta[768 + 2 * t + 1] = cs;
        }
    }
    __syncthreads();
    // unique-position table: u=0 shared by all invalid cols; u>=1 valid cols in order
    for (int u = t; u < NU2; u += 1024) {
        int pos = 0;
        if (u >= 1) {
            int v = u - 1;
            if (v < 4 * npos)              pos = d_colPos[v];
            else if (v < 6 * npos)         pos = d_colPos[512 + (v - 4 * npos)];
            else if (v < 6 * npos + 2 * K) pos = d_colPos[768 + (v - 6 * npos)];
        }
        d_uniqPos[u] = pos;
    }
}

// ---------------- fused prep: weight bf16-split + gather bf16-split ----------------
__global__ void prep_kernel(const float* __restrict__ W, const float* __restrict__ x) {
    if (blockIdx.x < WBLK) {
        int idx = blockIdx.x * 256 + threadIdx.x;   // CIN*KTOT
        int m = idx / KTOT;
        int k = idx - m * KTOT;
        float v = W[idx];
        __nv_bfloat16 hi = __float2bfloat16(v);
        __nv_bfloat16 lo = __float2bfloat16(v - __bfloat162float(hi));
        __nv_bfloat16* o = d_Wc + (size_t)m * K3;
        o[k] = hi; o[KTOT + k] = hi; o[2 * KTOT + k] = lo;
    } else {
        int idx = (blockIdx.x - WBLK) * 256 + threadIdx.x;   // NU2*KTOT
        int u = idx / KTOT;
        int k = idx - u * KTOT;
        if (u >= d_Upad) return;
        int s = d_uniqPos[u];
        int ci = k / 9;
        int r  = k - ci * 9;
        int ky = r / 3;
        int kx = r - ky * 3;
        int y  = (s >> 7) + ky - 1;
        int xx = (s & 127) + kx - 1;
        float v = 0.0f;
        if (((unsigned)y < 128u) && ((unsigned)xx < 128u))
            v = x[ci * HW + y * GW + xx];
        __nv_bfloat16 hi = __float2bfloat16(v);
        __nv_bfloat16 lo = __float2bfloat16(v - __bfloat162float(hi));
        __nv_bfloat16* o = d_Bc + (size_t)u * K3;
        o[k] = hi; o[KTOT + k] = lo; o[2 * KTOT + k] = hi;
    }
}

// ---------------- HMMA GEMM, cp.async 3-stage: d_hp[ks][u][m] = Wc @ Bc^T ----------------
// grid (17, 4, KSPLIT), 256 threads (8 warps: 4M x 2N), CTA tile 128x64, BK=64.
__global__ void __launch_bounds__(256) gemm_hmma(void) {
    int n0 = blockIdx.x * 64;
    if (n0 >= d_Upad) return;                  // dedup early-exit
    int m0 = blockIdx.y * 128;
    int ks = blockIdx.z;
    int kq0 = ks * KQ;

    extern __shared__ __nv_bfloat16 sm[];
    uint32_t smBase = smem_u32(sm);

    int t = threadIdx.x;
    int wid = t >> 5, lane = t & 31;
    int wm = wid & 3, wn = wid >> 2;

    float acc[2][4][4];
    #pragma unroll
    for (int i = 0; i < 2; i++)
        #pragma unroll
        for (int j = 0; j < 4; j++)
            #pragma unroll
            for (int e = 0; e < 4; e++) acc[i][j][e] = 0.0f;

    // per-thread cp.async slots: A 4x16B, B 2x16B per chunk
    const __nv_bfloat16* aG[4];
    const __nv_bfloat16* bG[2];
    uint32_t aS[4], bS[2];
    #pragma unroll
    for (int i = 0; i < 4; i++) {
        int u = i * 256 + t;
        int row = u >> 3, c16 = u & 7;
        aG[i] = d_Wc + (size_t)(m0 + row) * K3 + kq0 + c16 * 8;
        aS[i] = smBase + 2 * (uint32_t)(row * ASTRIDE + c16 * 8);
    }
    #pragma unroll
    for (int i = 0; i < 2; i++) {
        int u = i * 256 + t;
        int row = u >> 3, c16 = u & 7;
        bG[i] = d_Bc + (size_t)(n0 + row) * K3 + kq0 + c16 * 8;
        bS[i] = smBase + 2 * (uint32_t)(128 * ASTRIDE + row * ASTRIDE + c16 * 8);
    }

    #define ISSUE(ch) do {                                                     \
        uint32_t so = 2u * (uint32_t)(((ch) % 3) * STG);                       \
        int ko = (ch) * BK;                                                    \
        _Pragma("unroll")                                                      \
        for (int i = 0; i < 4; i++)                                            \
            asm volatile("cp.async.cg.shared.global [%0], [%1], 16;"           \
                :: "r"(aS[i] + so), "l"(aG[i] + ko) : "memory");               \
        _Pragma("unroll")                                                      \
        for (int i = 0; i < 2; i++)                                            \
            asm volatile("cp.async.cg.shared.global [%0], [%1], 16;"           \
                :: "r"(bS[i] + so), "l"(bG[i] + ko) : "memory");               \
        asm volatile("cp.async.commit_group;" ::: "memory");                   \
    } while (0)

    ISSUE(0);
    ISSUE(1);

    for (int ch = 0; ch < NCH; ch++) {
        if (ch + 1 < NCH) asm volatile("cp.async.wait_group 1;" ::: "memory");
        else              asm volatile("cp.async.wait_group 0;" ::: "memory");
        __syncthreads();
        if (ch + 2 < NCH) ISSUE(ch + 2);

        uint32_t so = 2u * (uint32_t)((ch % 3) * STG);
        #pragma unroll
        for (int s = 0; s < 4; s++) {          // 4 k16 steps per BK=64
            int koff = s * 16;
            uint32_t a[2][4], b[2][4];
            #pragma unroll
            for (int tm = 0; tm < 2; tm++) {
                uint32_t addr = smBase + so + 2 * (uint32_t)(
                    (wm * 32 + tm * 16 + (lane & 15)) * ASTRIDE + koff + ((lane >> 4) << 3));
                asm volatile("ldmatrix.sync.aligned.m8n8.x4.shared.b16 {%0,%1,%2,%3}, [%4];"
                    : "=r"(a[tm][0]), "=r"(a[tm][1]), "=r"(a[tm][2]), "=r"(a[tm][3]) : "r"(addr));
            }
            #pragma unroll
            for (int p = 0; p < 2; p++) {      // each x4 feeds 2 n-subtiles
                int g = lane >> 3;
                int row = wn * 32 + p * 16 + ((g >> 1) << 3) + (lane & 7);
                int kadd = (g & 1) << 3;
                uint32_t addr = smBase + so + 2 * (uint32_t)(
                    128 * ASTRIDE + row * ASTRIDE + koff + kadd);
                asm volatile("ldmatrix.sync.aligned.m8n8.x4.shared.b16 {%0,%1,%2,%3}, [%4];"
                    : "=r"(b[p][0]), "=r"(b[p][1]), "=r"(b[p][2]), "=r"(b[p][3]) : "r"(addr));
            }
            #pragma unroll
            for (int tm = 0; tm < 2; tm++)
                #pragma unroll
                for (int tn = 0; tn < 4; tn++) {
                    int p = tn >> 1, h = (tn & 1) << 1;
                    asm volatile(
                        "mma.sync.aligned.m16n8k16.row.col.f32.bf16.bf16.f32 "
                        "{%0,%1,%2,%3}, {%4,%5,%6,%7}, {%8,%9}, {%0,%1,%2,%3};"
                        : "+f"(acc[tm][tn][0]), "+f"(acc[tm][tn][1]),
                          "+f"(acc[tm][tn][2]), "+f"(acc[tm][tn][3])
                        : "r"(a[tm][0]), "r"(a[tm][1]), "r"(a[tm][2]), "r"(a[tm][3]),
                          "r"(b[p][h]), "r"(b[p][h + 1]));
                }
        }
        __syncthreads();
    }

    // epilogue: d_hp[ks][n][m]; lane g=lane>>2, tq=lane&3
    int g = lane >> 2, tq = lane & 3;
    float* hpBase = d_hp + (size_t)(ks * NU2) * CIN;
    #pragma unroll
    for (int tm = 0; tm < 2; tm++) {
        int rm = m0 + wm * 32 + tm * 16 + g;
        #pragma unroll
        for (int tn = 0; tn < 4; tn++) {
            int cn = n0 + wn * 32 + tn * 8 + tq * 2;
            hpBase[(size_t)cn * CIN + rm]           = acc[tm][tn][0];
            hpBase[(size_t)(cn + 1) * CIN + rm]     = acc[tm][tn][1];
            hpBase[(size_t)cn * CIN + rm + 8]       = acc[tm][tn][2];
            hpBase[(size_t)(cn + 1) * CIN + rm + 8] = acc[tm][tn][3];
        }
    }
}

// ---------------- per-column 1x1 conv dot (fused partial-reduce + bias + relu) ----------------
__global__ void coldot_kernel(const float* __restrict__ bw, const float* __restrict__ bb,
                              const float* __restrict__ sw, const float* __restrict__ sb,
                              const float* __restrict__ conv_b) {
    int col = blockIdx.x * 8 + (threadIdx.x >> 5);
    int lane = threadIdx.x & 31;
    int npos = d_nPos;
    int u;
    if (col < 512)      { int t = col >> 2;         u = (t < npos) ? 1 + col : 0; }
    else if (col < 768) { int t = (col - 512) >> 1; u = (t < npos) ? 1 + 4 * npos + (col - 512) : 0; }
    else                { int g = (col - 768) >> 1; u = (g < 256 - npos) ? 1 + 6 * npos + (col - 768) : 0; }
    if (u == 0) return;
    int meta = d_colMeta[col];
    const float* w;
    float b;
    if (meta < 36) { w = bw + meta * 512; b = bb[meta]; }
    else           { w = sw + (meta - 36) * 512; b = sb[meta - 36]; }
    const float4* wv = (const float4*)w;
    const float4* bias4 = (const float4*)conv_b;
    float s = 0.0f;
    for (int i = lane; i < 128; i += 32) {
        float4 a = bias4[i];
        #pragma unroll
        for (int ks = 0; ks < KSPLIT; ks++) {
            const float4* hp4 = (const float4*)(d_hp + (size_t)(ks * NU2 + u) * CIN);
            float4 hv = hp4[i];
            a.x += hv.x; a.y += hv.y; a.z += hv.z; a.w += hv.w;
        }
        a.x = fmaxf(a.x, 0.0f); a.y = fmaxf(a.y, 0.0f);
        a.z = fmaxf(a.z, 0.0f); a.w = fmaxf(a.w, 0.0f);
        float4 ww = wv[i];
        s += a.x * ww.x + a.y * ww.y + a.z * ww.z + a.w * ww.w;
    }
    #pragma unroll
    for (int o = 16; o > 0; o >>= 1) s += __shfl_xor_sync(0xFFFFFFFFu, s, o);
    if (lane == 0) d_val[col] = fmaxf(s + b, 0.0f);
}

// ---------------- loss ----------------
__global__ void loss_kernel(const float* __restrict__ target, float* __restrict__ out) {
    __shared__ float rce[256], rsl[256], rvc[256];
    int t = threadIdx.x;
    float ce = 0.0f, sl = 0.0f, vc = 0.0f;
    if (t < 128 && d_posValid[t]) {
        float s0 = d_val[512 + 2 * t], s1 = d_val[512 + 2 * t + 1];
        float m = fmaxf(s0, s1);
        float lse = m + logf(expf(s0 - m) + expf(s1 - m));
        ce += lse - s0;
        vc += 1.0f;
        int p = d_posIdx[t];
        int k = p % 9;
        int q = p / 9;
        int wq = q & 127;
        int hq = q >> 7;
        float ax1 = hq * STEP, ay1 = wq * STEP;
        float aw = d_whw[k], ah = d_whh[k];
        float acx = ax1 + aw * 0.5f, acy = ay1 + ah * 0.5f;
        float4 tb = ((const float4*)target)[d_tgtIdx[p]];
        float bw_ = tb.z - tb.x, bh_ = tb.w - tb.y;
        float bcx = tb.x + bw_ * 0.5f, bcy = tb.y + bh_ * 0.5f;
        float tr[4] = {(bcx - acx) / aw, (bcy - acy) / ah,
                       logf(bw_ / aw), logf(bh_ / ah)};
        #pragma unroll
        for (int e = 0; e < 4; e++) {
            float dd = d_val[4 * t + e] - tr[e];
            float ad = fabsf(dd);
            sl += (ad < 1.0f) ? 0.5f * dd * dd : (ad - 0.5f);
        }
    }
    if (t < 256 && d_negValid[t]) {
        float s0 = d_val[768 + 2 * t], s1 = d_val[768 + 2 * t + 1];
        float m = fmaxf(s0, s1);
        float lse = m + logf(expf(s0 - m) + expf(s1 - m));
        ce += lse - s1;
        vc += 1.0f;
    }
    rce[t] = ce; rsl[t] = sl; rvc[t] = vc;
    __syncthreads();
    for (int s2 = 128; s2 > 0; s2 >>= 1) {
        if (t < s2) { rce[t] += rce[t + s2]; rsl[t] += rsl[t + s2]; rvc[t] += rvc[t + s2]; }
        __syncthreads();
    }
    if (t == 0) {
        float np = (float)d_nPos;
        float score_loss = rce[0] / fmaxf(rvc[0], 1.0f);
        float reg_loss = rsl[0] / fmaxf(np * 4.0f, 1.0f);
        out[0] = score_loss + 10.0f * reg_loss;
    }
}

// ---------------- launch ----------------
extern "C" void kernel_launch(void* const* d_in, const int* in_sizes, int n_in,
                              void* d_out, int out_size) {
    const float* x       = (const float*)d_in[0];
    const float* target  = (const float*)d_in[1];
    const float* conv_w  = (const float*)d_in[2];
    const float* conv_b  = (const float*)d_in[3];
    const float* bbox_w  = (const float*)d_in[4];
    const float* bbox_b  = (const float*)d_in[5];
    const float* score_w = (const float*)d_in[6];
    const float* score_b = (const float*)d_in[7];
    float* out = (float*)d_out;

    // smem: 3 stages x (128+64)*72 halves * 2B = 82944 B
    const int DSMEM = 3 * STG * 2;
    cudaFuncSetAttribute(gemm_hmma, cudaFuncAttributeMaxDynamicSharedMemorySize, DSMEM);

    iou_kernel<<<NBLK, 256>>>(target);
    selection_kernel<<<1, 1024>>>();
    prep_kernel<<<WBLK + GBLK, 256>>>(conv_w, x);
    gemm_hmma<<<dim3(NU2 / 64, CIN / 128, KSPLIT), 256, DSMEM>>>();
    coldot_kernel<<<NCOL / 8, 256>>>(bbox_w, bbox_b, score_w, score_b, conv_b);
    loss_kernel<<<1, 256>>>(target, out);
}

// round 14
// speedup vs baseline: 1.9889x; 1.0563x over previous
#include <cuda_runtime.h>
#include <cuda_bf16.h>
#include <math.h>
#include <stdint.h>

#define A_TOT 147456      // 128*128*9 anchors
#define HW    16384
#define GW    128
#define CIN   512
#define KTOT  4608        // 512*9
#define K2    9216        // 2*KTOT storage (hi, lo)
#define KSPLIT 12
#define KQ    1152        // logical K3 / KSPLIT  (13824/12)
#define BK    64
#define NCH   18          // KQ/BK
#define NCOL  1280
#define NU2   1152        // max unique columns padded to 128 (9 tiles)
#define NBLK  576
#define STEP  (2048.0f/127.0f)
#define ASTRIDE 72        // smem row stride in halves (64 + 8 pad)
#define STG   (256 * ASTRIDE)          // halves per stage (128 A rows + 128 B rows)
#define WBLK  9216        // wconv blocks: CIN*KTOT/256
#define GBLK  20736       // gather blocks: NU2*KTOT/256
#define WREG  4608        // anchors per warp in selection (A_TOT/32)
#define WROWS 144

__constant__ float d_whw[9] = {128.0f, 181.01933598375618f, 90.50966799187809f,
                               256.0f, 362.03867196751236f, 181.01933598375618f,
                               512.0f, 724.0773439350247f, 362.03867196751236f};
__constant__ float d_whh[9] = {128.0f, 90.50966799187809f, 181.01933598375618f,
                               256.0f, 181.01933598375618f, 362.03867196751236f,
                               512.0f, 362.03867196751236f, 724.0773439350247f};

// ---------------- static device scratch ----------------
__device__ float d_maxIou[A_TOT];
__device__ int   d_tgtIdx[A_TOT];
__device__ int   d_posIdx[128];
__device__ int   d_posValid[128];
__device__ int   d_negValid[256];
__device__ int   d_nPos;
__device__ int   d_Upad;              // padded to 128
__device__ int   d_colPos[NCOL];
__device__ int   d_colMeta[NCOL];
__device__ int   d_uniqPos[NU2];
__device__ __align__(16) __nv_bfloat16 d_Wc[(size_t)CIN * K2];   // [m][hi(4608), lo(4608)]
__device__ __align__(16) __nv_bfloat16 d_Bc[(size_t)NU2 * K2];   // [u][hi(4608), lo(4608)]
__device__ float d_hp[KSPLIT * NU2 * CIN];                        // partials [ks][u][m]
__device__ float d_val[NCOL];

__device__ __forceinline__ uint32_t smem_u32(const void* p) {
    uint32_t a;
    asm("{ .reg .u64 t; cvta.to.shared.u64 t, %1; cvt.u32.u64 %0, t; }" : "=r"(a) : "l"(p));
    return a;
}

// ---------------- phase A: IoU matching ----------------
__global__ void iou_kernel(const float* __restrict__ target) {
    __shared__ float4 tg[64];
    int t = threadIdx.x;
    if (t < 64) tg[t] = ((const float4*)target)[t];
    __syncthreads();
    int a = blockIdx.x * 256 + t;
    int k = a % 9;
    int q = a / 9;
    int wq = q & 127;
    int hq = q >> 7;
    float x1 = hq * STEP;
    float y1 = wq * STEP;
    float x2 = x1 + d_whw[k];
    float y2 = y1 + d_whh[k];
    float areaA = (x2 - x1) * (y2 - y1);
    float best = -1.0f;
    int bi = 0;
    #pragma unroll 4
    for (int i = 0; i < 64; i++) {
        float4 b = tg[i];
        float lx = fmaxf(b.x, x1), ly = fmaxf(b.y, y1);
        float rx = fminf(b.z, x2), ry = fminf(b.w, y2);
        float iw = fmaxf(rx - lx, 0.0f), ih = fmaxf(ry - ly, 0.0f);
        float inter = iw * ih;
        float at = (b.z - b.x) * (b.w - b.y);
        float iou = inter / (at + areaA - inter);
        if (iou > best) { best = iou; bi = i; }   // first-max == jnp.argmax
    }
    d_maxIou[a] = best;
    d_tgtIdx[a] = bi;
}

// ---------------- fallback sort (1024 threads) ----------------
__device__ __forceinline__ void bitonic2048(unsigned long long* s) {
    int t = threadIdx.x;
    for (int k = 2; k <= 2048; k <<= 1) {
        for (int j = k >> 1; j > 0; j >>= 1) {
            __syncthreads();
            #pragma unroll
            for (int base = 0; base < 2048; base += 1024) {
                int i = base + t;
                int ixj = i ^ j;
                if (ixj > i) {
                    unsigned long long va = s[i], vb = s[ixj];
                    bool sw = ((i & k) == 0) ? (va < vb) : (va > vb);
                    if (sw) { s[i] = vb; s[ixj] = va; }
                }
            }
        }
    }
    __syncthreads();
}

// ---------------- phase B: warp-parallel two-pass selection + column tables ----------------
__global__ void selection_kernel() {   // 1 block x 1024
    __shared__ unsigned long long pKeys[2048];
    __shared__ int zIdx[256];
    __shared__ int warpZ[32], warpP[32];
    __shared__ int zExS[32], pExS[32];
    __shared__ int pTotS;
    int t = threadIdx.x, lane = t & 31, w = t >> 5;
    unsigned lmLT = (1u << lane) - 1u;
    int wbase = w * WREG;

    // pass 1: per-warp class counts
    int nzW = 0, npW = 0;
    #pragma unroll 4
    for (int i = 0; i < WROWS; i++) {
        float v = d_maxIou[wbase + i * 32 + lane];
        bool z = (v < 0.3f) && ((1.0f - v) == 1.0f);   // exact ref tie-class
        bool p = (v > 0.7f);
        nzW += __popc(__ballot_sync(0xFFFFFFFFu, z));
        npW += __popc(__ballot_sync(0xFFFFFFFFu, p));
    }
    if (lane == 0) { warpZ[w] = nzW; warpP[w] = npW; }
    __syncthreads();
    if (w == 0) {
        int vz = warpZ[lane], vp = warpP[lane];
        int sz = vz, sp = vp;
        #pragma unroll
        for (int o = 1; o < 32; o <<= 1) {
            int xz = __shfl_up_sync(0xFFFFFFFFu, sz, o);
            int xp = __shfl_up_sync(0xFFFFFFFFu, sp, o);
            if (lane >= o) { sz += xz; sp += xp; }
        }
        zExS[lane] = sz - vz;
        pExS[lane] = sp - vp;
        if (lane == 31) pTotS = sp;
    }
    __syncthreads();

    // pass 2: replay with running bases; exact index-order ranks
    {
        int zr = zExS[w], pr = pExS[w];
        if (zr < 256 || pr < 2048) {
            for (int i = 0; i < WROWS; i++) {
                int a = wbase + i * 32 + lane;
                float v = d_maxIou[a];
                bool z = (v < 0.3f) && ((1.0f - v) == 1.0f);
                bool p = (v > 0.7f);
                unsigned bz = __ballot_sync(0xFFFFFFFFu, z);
                unsigned bp = __ballot_sync(0xFFFFFFFFu, p);
                if (z) {
                    int r = zr + __popc(bz & lmLT);
                    if (r < 256) zIdx[r] = a;
                }
                if (p) {
                    int r = pr + __popc(bp & lmLT);
                    if (r < 2048)
                        pKeys[r] = (((unsigned long long)__float_as_uint(v) << 32) |
                                    (0xFFFFFFFFu - (unsigned)a));
                }
                zr += __popc(bz);
                pr += __popc(bp);
                if (zr >= 256 && pr >= 2048) break;
            }
        }
    }
    __syncthreads();

    int cnt = pTotS;
    int npos = cnt < 128 ? cnt : 128;
    int K = 256 - npos;
    if (t == 0) {
        d_nPos = npos;
        int U = 513 + 4 * npos;
        d_Upad = (U + 127) & ~127;   // pad to 128 (GEMM N-tile)
    }
    if (cnt > 128) {
        int stored = cnt < 2048 ? cnt : 2048;
        for (int i = t; i < 2048; i += 1024)
            if (i >= stored) pKeys[i] = 0ULL;
        __syncthreads();
        bitonic2048(pKeys);
    }
    __syncthreads();
    if (t < 128) {
        int valid = (t < npos);
        d_posValid[t] = valid;
        if (valid) {
            int p = (int)(0xFFFFFFFFu - (unsigned)(pKeys[t] & 0xFFFFFFFFULL));
            d_posIdx[t] = p;
            int sb = (4 * p) & 16383;
            int ssc = (2 * p) & 16383;
            int cb = p >> 12;
            int cs = 36 + (p >> 13);
            #pragma unroll
            for (int e = 0; e < 4; e++) {
                d_colPos[4 * t + e] = sb + e;
                d_colMeta[4 * t + e] = cb;
            }
            #pragma unroll
            for (int e = 0; e < 2; e++) {
                d_colPos[512 + 2 * t + e] = ssc + e;
                d_colMeta[512 + 2 * t + e] = cs;
            }
        }
    }
    if (t < 256) {
        d_negValid[t] = (t < K);
        if (t < K) {
            int a = zIdx[t];
            int ss = (2 * a) & 16383;
            int cs = 36 + (a >> 13);
            d_colPos[768 + 2 * t] = ss;         d_colMeta[768 + 2 * t] = cs;
            d_colPos[768 + 2 * t + 1] = ss + 1; d_colMeta[768 + 2 * t + 1] = cs;
        }
    }
    __syncthreads();
    for (int u = t; u < NU2; u += 1024) {
        int pos = 0;
        if (u >= 1) {
            int v = u - 1;
            if (v < 4 * npos)              pos = d_colPos[v];
            else if (v < 6 * npos)         pos = d_colPos[512 + (v - 4 * npos)];
            else if (v < 6 * npos + 2 * K) pos = d_colPos[768 + (v - 6 * npos)];
        }
        d_uniqPos[u] = pos;
    }
}

// ---------------- fused prep: weight bf16-split + gather bf16-split ([hi,lo]) ----------------
__global__ void prep_kernel(const float* __restrict__ W, const float* __restrict__ x) {
    if (blockIdx.x < WBLK) {
        int idx = blockIdx.x * 256 + threadIdx.x;   // CIN*KTOT
        int m = idx / KTOT;
        int k = idx - m * KTOT;
        float v = W[idx];
        __nv_bfloat16 hi = __float2bfloat16(v);
        __nv_bfloat16 lo = __float2bfloat16(v - __bfloat162float(hi));
        __nv_bfloat16* o = d_Wc + (size_t)m * K2;
        o[k] = hi; o[KTOT + k] = lo;
    } else {
        int idx = (blockIdx.x - WBLK) * 256 + threadIdx.x;   // NU2*KTOT
        int u = idx / KTOT;
        int k = idx - u * KTOT;
        if (u >= d_Upad) return;
        int s = d_uniqPos[u];
        int ci = k / 9;
        int r  = k - ci * 9;
        int ky = r / 3;
        int kx = r - ky * 3;
        int y  = (s >> 7) + ky - 1;
        int xx = (s & 127) + kx - 1;
        float v = 0.0f;
        if (((unsigned)y < 128u) && ((unsigned)xx < 128u))
            v = x[ci * HW + y * GW + xx];
        __nv_bfloat16 hi = __float2bfloat16(v);
        __nv_bfloat16 lo = __float2bfloat16(v - __bfloat162float(hi));
        __nv_bfloat16* o = d_Bc + (size_t)u * K2;
        o[k] = hi; o[KTOT + k] = lo;
    }
}

// ---------------- HMMA GEMM, cp.async 3-stage, CTA 128x128, warp 32x64 ----------------
// Logical K' = 13824 as 3 terms [WhiBhi, WhiBlo, WloBhi] over dedup [hi,lo] storage.
// grid (9, 4, KSPLIT=12), 256 threads (8 warps: 4M x 2N).
__global__ void __launch_bounds__(256, 2) gemm_hmma(void) {
    int n0 = blockIdx.x * 128;
    if (n0 >= d_Upad) return;                  // dedup early-exit
    int m0 = blockIdx.y * 128;
    int ks = blockIdx.z;
    int kq0 = ks * KQ;
    int aOff = kq0 - ((ks >= 4) ? KTOT : 0);   // Whi for ks<8-chunk terms 0,1; Wlo term 2
    int bOff = (ks >= 8) ? (kq0 - 2 * KTOT) : kq0;  // Bhi, Blo, Bhi

    extern __shared__ __nv_bfloat16 sm[];
    uint32_t smBase = smem_u32(sm);

    int t = threadIdx.x;
    int wid = t >> 5, lane = t & 31;
    int wm = wid & 3, wn = wid >> 2;

    float acc[2][8][4];
    #pragma unroll
    for (int i = 0; i < 2; i++)
        #pragma unroll
        for (int j = 0; j < 8; j++)
            #pragma unroll
            for (int e = 0; e < 4; e++) acc[i][j][e] = 0.0f;

    // per-thread cp.async: 4 A slots + 4 B slots (row = t>>3 + 32*i, c16 = t&7)
    int row = t >> 3, c16 = t & 7;
    const __nv_bfloat16* aG0 = d_Wc + (size_t)(m0 + row) * K2 + aOff + c16 * 8;
    const __nv_bfloat16* bG0 = d_Bc + (size_t)(n0 + row) * K2 + bOff + c16 * 8;
    uint32_t aS0 = smBase + 2 * (uint32_t)(row * ASTRIDE + c16 * 8);
    uint32_t bS0 = smBase + 2 * (uint32_t)(128 * ASTRIDE + row * ASTRIDE + c16 * 8);

    #define ISSUE(ch) do {                                                     \
        uint32_t so = 2u * (uint32_t)(((ch) % 3) * STG);                       \
        int ko = (ch) * BK;                                                    \
        _Pragma("unroll")                                                      \
        for (int i = 0; i < 4; i++)                                            \
            asm volatile("cp.async.cg.shared.global [%0], [%1], 16;"           \
                :: "r"(aS0 + so + 2u * (uint32_t)(i * 32 * ASTRIDE)),          \
                   "l"(aG0 + (size_t)i * 32 * K2 + ko) : "memory");            \
        _Pragma("unroll")                                                      \
        for (int i = 0; i < 4; i++)                                            \
            asm volatile("cp.async.cg.shared.global [%0], [%1], 16;"           \
                :: "r"(bS0 + so + 2u * (uint32_t)(i * 32 * ASTRIDE)),          \
                   "l"(bG0 + (size_t)i * 32 * K2 + ko) : "memory");            \
        asm volatile("cp.async.commit_group;" ::: "memory");                   \
    } while (0)

    ISSUE(0);
    ISSUE(1);

    for (int ch = 0; ch < NCH; ch++) {
        if (ch + 1 < NCH) asm volatile("cp.async.wait_group 1;" ::: "memory");
        else              asm volatile("cp.async.wait_group 0;" ::: "memory");
        __syncthreads();
        if (ch + 2 < NCH) ISSUE(ch + 2);

        uint32_t so = 2u * (uint32_t)((ch % 3) * STG);
        #pragma unroll
        for (int s = 0; s < 4; s++) {          // 4 k16 steps per BK=64
            int koff = s * 16;
            uint32_t a[2][4], b[4][4];
            #pragma unroll
            for (int tm = 0; tm < 2; tm++) {
                uint32_t addr = smBase + so + 2 * (uint32_t)(
                    (wm * 32 + tm * 16 + (lane & 15)) * ASTRIDE + koff + ((lane >> 4) << 3));
                asm volatile("ldmatrix.sync.aligned.m8n8.x4.shared.b16 {%0,%1,%2,%3}, [%4];"
                    : "=r"(a[tm][0]), "=r"(a[tm][1]), "=r"(a[tm][2]), "=r"(a[tm][3]) : "r"(addr));
            }
            #pragma unroll
            for (int p = 0; p < 4; p++) {      // each x4 feeds 2 n-subtiles
                int g = lane >> 3;
                int brow = wn * 64 + p * 16 + ((g >> 1) << 3) + (lane & 7);
                int kadd = (g & 1) << 3;
                uint32_t addr = smBase + so + 2 * (uint32_t)(
                    128 * ASTRIDE + brow * ASTRIDE + koff + kadd);
                asm volatile("ldmatrix.sync.aligned.m8n8.x4.shared.b16 {%0,%1,%2,%3}, [%4];"
                    : "=r"(b[p][0]), "=r"(b[p][1]), "=r"(b[p][2]), "=r"(b[p][3]) : "r"(addr));
            }
            #pragma unroll
            for (int tm = 0; tm < 2; tm++)
                #pragma unroll
                for (int tn = 0; tn < 8; tn++) {
                    int p = tn >> 1, h = (tn & 1) << 1;
                    asm volatile(
                        "mma.sync.aligned.m16n8k16.row.col.f32.bf16.bf16.f32 "
                        "{%0,%1,%2,%3}, {%4,%5,%6,%7}, {%8,%9}, {%0,%1,%2,%3};"
                        : "+f"(acc[tm][tn][0]), "+f"(acc[tm][tn][1]),
                          "+f"(acc[tm][tn][2]), "+f"(acc[tm][tn][3])
                        : "r"(a[tm][0]), "r"(a[tm][1]), "r"(a[tm][2]), "r"(a[tm][3]),
                          "r"(b[p][h]), "r"(b[p][h + 1]));
                }
        }
        __syncthreads();
    }

    // epilogue: d_hp[ks][n][m]; lane g=lane>>2, tq=lane&3
    int g = lane >> 2, tq = lane & 3;
    float* hpBase = d_hp + (size_t)(ks * NU2) * CIN;
    #pragma unroll
    for (int tm = 0; tm < 2; tm++) {
        int rm = m0 + wm * 32 + tm * 16 + g;
        #pragma unroll
        for (int tn = 0; tn < 8; tn++) {
            int cn = n0 + wn * 64 + tn * 8 + tq * 2;
            hpBase[(size_t)cn * CIN + rm]           = acc[tm][tn][0];
            hpBase[(size_t)(cn + 1) * CIN + rm]     = acc[tm][tn][1];
            hpBase[(size_t)cn * CIN + rm + 8]       = acc[tm][tn][2];
            hpBase[(size_t)(cn + 1) * CIN + rm + 8] = acc[tm][tn][3];
        }
    }
}

// ---------------- per-column 1x1 conv dot (fused partial-reduce + bias + relu) ----------------
__global__ void coldot_kernel(const float* __restrict__ bw, const float* __restrict__ bb,
                              const float* __restrict__ sw, const float* __restrict__ sb,
                              const float* __restrict__ conv_b) {
    int col = blockIdx.x * 8 + (threadIdx.x >> 5);
    int lane = threadIdx.x & 31;
    int npos = d_nPos;
    int u;
    if (col < 512)      { int t = col >> 2;         u = (t < npos) ? 1 + col : 0; }
    else if (col < 768) { int t = (col - 512) >> 1; u = (t < npos) ? 1 + 4 * npos + (col - 512) : 0; }
    else                { int g = (col - 768) >> 1; u = (g < 256 - npos) ? 1 + 6 * npos + (col - 768) : 0; }
    if (u == 0) return;
    int meta = d_colMeta[col];
    const float* w;
    float b;
    if (meta < 36) { w = bw + meta * 512; b = bb[meta]; }
    else           { w = sw + (meta - 36) * 512; b = sb[meta - 36]; }
    const float4* wv = (const float4*)w;
    const float4* bias4 = (const float4*)conv_b;
    float s = 0.0f;
    for (int i = lane; i < 128; i += 32) {
        float4 a = bias4[i];
        #pragma unroll
        for (int ks = 0; ks < KSPLIT; ks++) {
            const float4* hp4 = (const float4*)(d_hp + (size_t)(ks * NU2 + u) * CIN);
            float4 hv = hp4[i];
            a.x += hv.x; a.y += hv.y; a.z += hv.z; a.w += hv.w;
        }
        a.x = fmaxf(a.x, 0.0f); a.y = fmaxf(a.y, 0.0f);
        a.z = fmaxf(a.z, 0.0f); a.w = fmaxf(a.w, 0.0f);
        float4 ww = wv[i];
        s += a.x * ww.x + a.y * ww.y + a.z * ww.z + a.w * ww.w;
    }
    #pragma unroll
    for (int o = 16; o > 0; o >>= 1) s += __shfl_xor_sync(0xFFFFFFFFu, s, o);
    if (lane == 0) d_val[col] = fmaxf(s + b, 0.0f);
}

// ---------------- loss ----------------
__global__ void loss_kernel(const float* __restrict__ target, float* __restrict__ out) {
    __shared__ float rce[256], rsl[256], rvc[256];
    int t = threadIdx.x;
    float ce = 0.0f, sl = 0.0f, vc = 0.0f;
    if (t < 128 && d_posValid[t]) {
        float s0 = d_val[512 + 2 * t], s1 = d_val[512 + 2 * t + 1];
        float m = fmaxf(s0, s1);
        float lse = m + logf(expf(s0 - m) + expf(s1 - m));
        ce += lse - s0;
        vc += 1.0f;
        int p = d_posIdx[t];
        int k = p % 9;
        int q = p / 9;
        int wq = q & 127;
        int hq = q >> 7;
        float ax1 = hq * STEP, ay1 = wq * STEP;
        float aw = d_whw[k], ah = d_whh[k];
        float acx = ax1 + aw * 0.5f, acy = ay1 + ah * 0.5f;
        float4 tb = ((const float4*)target)[d_tgtIdx[p]];
        float bw_ = tb.z - tb.x, bh_ = tb.w - tb.y;
        float bcx = tb.x + bw_ * 0.5f, bcy = tb.y + bh_ * 0.5f;
        float tr[4] = {(bcx - acx) / aw, (bcy - acy) / ah,
                       logf(bw_ / aw), logf(bh_ / ah)};
        #pragma unroll
        for (int e = 0; e < 4; e++) {
            float dd = d_val[4 * t + e] - tr[e];
            float ad = fabsf(dd);
            sl += (ad < 1.0f) ? 0.5f * dd * dd : (ad - 0.5f);
        }
    }
    if (t < 256 && d_negValid[t]) {
        float s0 = d_val[768 + 2 * t], s1 = d_val[768 + 2 * t + 1];
        float m = fmaxf(s0, s1);
        float lse = m + logf(expf(s0 - m) + expf(s1 - m));
        ce += lse - s1;
        vc += 1.0f;
    }
    rce[t] = ce; rsl[t] = sl; rvc[t] = vc;
    __syncthreads();
    for (int s2 = 128; s2 > 0; s2 >>= 1) {
        if (t < s2) { rce[t] += rce[t + s2]; rsl[t] += rsl[t + s2]; rvc[t] += rvc[t + s2]; }
        __syncthreads();
    }
    if (t == 0) {
        float np = (float)d_nPos;
        float score_loss = rce[0] / fmaxf(rvc[0], 1.0f);
        float reg_loss = rsl[0] / fmaxf(np * 4.0f, 1.0f);
        out[0] = score_loss + 10.0f * reg_loss;
    }
}

// ---------------- launch ----------------
extern "C" void kernel_launch(void* const* d_in, const int* in_sizes, int n_in,
                              void* d_out, int out_size) {
    const float* x       = (const float*)d_in[0];
    const float* target  = (const float*)d_in[1];
    const float* conv_w  = (const float*)d_in[2];
    const float* conv_b  = (const float*)d_in[3];
    const float* bbox_w  = (const float*)d_in[4];
    const float* bbox_b  = (const float*)d_in[5];
    const float* score_w = (const float*)d_in[6];
    const float* score_b = (const float*)d_in[7];
    float* out = (float*)d_out;

    // smem: 3 stages x 256*72 halves * 2B = 110592 B
    const int DSMEM = 3 * STG * 2;
    cudaFuncSetAttribute(gemm_hmma, cudaFuncAttributeMaxDynamicSharedMemorySize, DSMEM);

    iou_kernel<<<NBLK, 256>>>(target);
    selection_kernel<<<1, 1024>>>();
    prep_kernel<<<WBLK + GBLK, 256>>>(conv_w, x);
    gemm_hmma<<<dim3(NU2 / 128, CIN / 128, KSPLIT), 256, DSMEM>>>();
    coldot_kernel<<<NCOL / 8, 256>>>(bbox_w, bbox_b, score_w, score_b, conv_b);
    loss_kernel<<<1, 256>>>(target, out);
}

// round 15
// speedup vs baseline: 2.1257x; 1.0688x over previous
#include <cuda_runtime.h>
#include <cuda_bf16.h>
#include <math.h>
#include <stdint.h>

#define A_TOT 147456      // 128*128*9 anchors
#define HW    16384
#define GW    128
#define CIN   512
#define KTOT  4608        // 512*9
#define K2    9216        // 2*KTOT storage (hi, lo)
#define KSPLIT 12
#define KQ    1152        // logical K3 / KSPLIT  (13824/12)
#define BK    64
#define NCH   18          // KQ/BK
#define NCOL  1280
#define NU2   1152        // max unique columns padded to 128 (9 tiles)
#define NBLK  576
#define STEP  (2048.0f/127.0f)
#define ASTRIDE 72        // smem row stride in halves (64 + 8 pad)
#define STG   (256 * ASTRIDE)          // halves per stage (128 A rows + 128 B rows)
#define FST   132         // epilogue staging stride in floats (128 + 4)
#define WBLK  9216        // wconv blocks: CIN*KTOT/256
#define GBLK  20736       // gather blocks: NU2*KTOT/256
#define WREG  4608        // anchors per warp in selection (A_TOT/32)
#define WROWS 144

__constant__ float d_whw[9] = {128.0f, 181.01933598375618f, 90.50966799187809f,
                               256.0f, 362.03867196751236f, 181.01933598375618f,
                               512.0f, 724.0773439350247f, 362.03867196751236f};
__constant__ float d_whh[9] = {128.0f, 90.50966799187809f, 181.01933598375618f,
                               256.0f, 181.01933598375618f, 362.03867196751236f,
                               512.0f, 362.03867196751236f, 724.0773439350247f};

// ---------------- static device scratch ----------------
__device__ float d_maxIou[A_TOT];
__device__ int   d_tgtIdx[A_TOT];
__device__ int   d_posIdx[128];
__device__ int   d_posValid[128];
__device__ int   d_negValid[256];
__device__ int   d_nPos;
__device__ int   d_Upad;              // padded to 128
__device__ int   d_colPos[NCOL];
__device__ int   d_colMeta[NCOL];
__device__ int   d_uniqPos[NU2];
__device__ __align__(16) __nv_bfloat16 d_Wc[(size_t)CIN * K2];   // [m][hi(4608), lo(4608)]
__device__ __align__(16) __nv_bfloat16 d_Bc[(size_t)NU2 * K2];   // [u][hi(4608), lo(4608)]
__device__ float d_hp[KSPLIT * NU2 * CIN];                        // partials [ks][u][m]
__device__ float d_val[NCOL];

__device__ __forceinline__ uint32_t smem_u32(const void* p) {
    uint32_t a;
    asm("{ .reg .u64 t; cvta.to.shared.u64 t, %1; cvt.u32.u64 %0, t; }" : "=r"(a) : "l"(p));
    return a;
}

// ---------------- phase A: IoU matching (division-free running max) ----------------
__global__ void iou_kernel(const float* __restrict__ target) {
    __shared__ float4 tg[64];
    int t = threadIdx.x;
    if (t < 64) tg[t] = ((const float4*)target)[t];
    __syncthreads();
    int a = blockIdx.x * 256 + t;
    int k = a % 9;
    int q = a / 9;
    int wq = q & 127;
    int hq = q >> 7;
    float x1 = hq * STEP;
    float y1 = wq * STEP;
    float x2 = x1 + d_whw[k];
    float y2 = y1 + d_whh[k];
    float areaA = (x2 - x1) * (y2 - y1);

    // running max of inter_i/denom_i via cross-multiplication (denoms > 0).
    // strict > keeps the FIRST index on exact ties == jnp.argmax semantics.
    float bestN = -1.0f, bestD = 1.0f;
    int bi = 0;
    #pragma unroll 4
    for (int i = 0; i < 64; i++) {
        float4 b = tg[i];
        float lx = fmaxf(b.x, x1), ly = fmaxf(b.y, y1);
        float rx = fminf(b.z, x2), ry = fminf(b.w, y2);
        float iw = fmaxf(rx - lx, 0.0f), ih = fmaxf(ry - ly, 0.0f);
        float inter = iw * ih;
        float at = (b.z - b.x) * (b.w - b.y);
        float denom = at + areaA - inter;
        if (inter * bestD > bestN * denom) { bestN = inter; bestD = denom; bi = i; }
    }
    d_maxIou[a] = bestN / bestD;   // same fp32 quotient the reference computes
    d_tgtIdx[a] = bi;
}

// ---------------- fallback sort (1024 threads) ----------------
__device__ __forceinline__ void bitonic2048(unsigned long long* s) {
    int t = threadIdx.x;
    for (int k = 2; k <= 2048; k <<= 1) {
        for (int j = k >> 1; j > 0; j >>= 1) {
            __syncthreads();
            #pragma unroll
            for (int base = 0; base < 2048; base += 1024) {
                int i = base + t;
                int ixj = i ^ j;
                if (ixj > i) {
                    unsigned long long va = s[i], vb = s[ixj];
                    bool sw = ((i & k) == 0) ? (va < vb) : (va > vb);
                    if (sw) { s[i] = vb; s[ixj] = va; }
                }
            }
        }
    }
    __syncthreads();
}

// ---------------- phase B: warp-parallel two-pass selection + column tables ----------------
__global__ void selection_kernel() {   // 1 block x 1024
    __shared__ unsigned long long pKeys[2048];
    __shared__ int zIdx[256];
    __shared__ int warpZ[32], warpP[32];
    __shared__ int zExS[32], pExS[32];
    __shared__ int pTotS;
    int t = threadIdx.x, lane = t & 31, w = t >> 5;
    unsigned lmLT = (1u << lane) - 1u;
    int wbase = w * WREG;

    // pass 1: per-warp class counts
    int nzW = 0, npW = 0;
    #pragma unroll 4
    for (int i = 0; i < WROWS; i++) {
        float v = d_maxIou[wbase + i * 32 + lane];
        bool z = (v < 0.3f) && ((1.0f - v) == 1.0f);   // exact ref tie-class
        bool p = (v > 0.7f);
        nzW += __popc(__ballot_sync(0xFFFFFFFFu, z));
        npW += __popc(__ballot_sync(0xFFFFFFFFu, p));
    }
    if (lane == 0) { warpZ[w] = nzW; warpP[w] = npW; }
    __syncthreads();
    if (w == 0) {
        int vz = warpZ[lane], vp = warpP[lane];
        int sz = vz, sp = vp;
        #pragma unroll
        for (int o = 1; o < 32; o <<= 1) {
            int xz = __shfl_up_sync(0xFFFFFFFFu, sz, o);
            int xp = __shfl_up_sync(0xFFFFFFFFu, sp, o);
            if (lane >= o) { sz += xz; sp += xp; }
        }
        zExS[lane] = sz - vz;
        pExS[lane] = sp - vp;
        if (lane == 31) pTotS = sp;
    }
    __syncthreads();

    // pass 2: replay with running bases; exact index-order ranks
    {
        int zr = zExS[w], pr = pExS[w];
        if (zr < 256 || pr < 2048) {
            for (int i = 0; i < WROWS; i++) {
                int a = wbase + i * 32 + lane;
                float v = d_maxIou[a];
                bool z = (v < 0.3f) && ((1.0f - v) == 1.0f);
                bool p = (v > 0.7f);
                unsigned bz = __ballot_sync(0xFFFFFFFFu, z);
                unsigned bp = __ballot_sync(0xFFFFFFFFu, p);
                if (z) {
                    int r = zr + __popc(bz & lmLT);
                    if (r < 256) zIdx[r] = a;
                }
                if (p) {
                    int r = pr + __popc(bp & lmLT);
                    if (r < 2048)
                        pKeys[r] = (((unsigned long long)__float_as_uint(v) << 32) |
                                    (0xFFFFFFFFu - (unsigned)a));
                }
                zr += __popc(bz);
                pr += __popc(bp);
                if (zr >= 256 && pr >= 2048) break;
            }
        }
    }
    __syncthreads();

    int cnt = pTotS;
    int npos = cnt < 128 ? cnt : 128;
    int K = 256 - npos;
    if (t == 0) {
        d_nPos = npos;
        int U = 513 + 4 * npos;
        d_Upad = (U + 127) & ~127;   // pad to 128 (GEMM N-tile)
    }
    if (cnt > 128) {
        int stored = cnt < 2048 ? cnt : 2048;
        for (int i = t; i < 2048; i += 1024)
            if (i >= stored) pKeys[i] = 0ULL;
        __syncthreads();
        bitonic2048(pKeys);
    }
    __syncthreads();
    if (t < 128) {
        int valid = (t < npos);
        d_posValid[t] = valid;
        if (valid) {
            int p = (int)(0xFFFFFFFFu - (unsigned)(pKeys[t] & 0xFFFFFFFFULL));
            d_posIdx[t] = p;
            int sb = (4 * p) & 16383;
            int ssc = (2 * p) & 16383;
            int cb = p >> 12;
            int cs = 36 + (p >> 13);
            #pragma unroll
            for (int e = 0; e < 4; e++) {
                d_colPos[4 * t + e] = sb + e;
                d_colMeta[4 * t + e] = cb;
            }
            #pragma unroll
            for (int e = 0; e < 2; e++) {
                d_colPos[512 + 2 * t + e] = ssc + e;
                d_colMeta[512 + 2 * t + e] = cs;
            }
        }
    }
    if (t < 256) {
        d_negValid[t] = (t < K);
        if (t < K) {
            int a = zIdx[t];
            int ss = (2 * a) & 16383;
            int cs = 36 + (a >> 13);
            d_colPos[768 + 2 * t] = ss;         d_colMeta[768 + 2 * t] = cs;
            d_colPos[768 + 2 * t + 1] = ss + 1; d_colMeta[768 + 2 * t + 1] = cs;
        }
    }
    __syncthreads();
    for (int u = t; u < NU2; u += 1024) {
        int pos = 0;
        if (u >= 1) {
            int v = u - 1;
            if (v < 4 * npos)              pos = d_colPos[v];
            else if (v < 6 * npos)         pos = d_colPos[512 + (v - 4 * npos)];
            else if (v < 6 * npos + 2 * K) pos = d_colPos[768 + (v - 6 * npos)];
        }
        d_uniqPos[u] = pos;
    }
}

// ---------------- fused prep: weight bf16-split + gather bf16-split ([hi,lo]) ----------------
__global__ void prep_kernel(const float* __restrict__ W, const float* __restrict__ x) {
    if (blockIdx.x < WBLK) {
        int idx = blockIdx.x * 256 + threadIdx.x;   // CIN*KTOT
        int m = idx / KTOT;
        int k = idx - m * KTOT;
        float v = W[idx];
        __nv_bfloat16 hi = __float2bfloat16(v);
        __nv_bfloat16 lo = __float2bfloat16(v - __bfloat162float(hi));
        __nv_bfloat16* o = d_Wc + (size_t)m * K2;
        o[k] = hi; o[KTOT + k] = lo;
    } else {
        int idx = (blockIdx.x - WBLK) * 256 + threadIdx.x;   // NU2*KTOT
        int u = idx / KTOT;
        int k = idx - u * KTOT;
        if (u >= d_Upad) return;
        int s = d_uniqPos[u];
        int ci = k / 9;
        int r  = k - ci * 9;
        int ky = r / 3;
        int kx = r - ky * 3;
        int y  = (s >> 7) + ky - 1;
        int xx = (s & 127) + kx - 1;
        float v = 0.0f;
        if (((unsigned)y < 128u) && ((unsigned)xx < 128u))
            v = x[ci * HW + y * GW + xx];
        __nv_bfloat16 hi = __float2bfloat16(v);
        __nv_bfloat16 lo = __float2bfloat16(v - __bfloat162float(hi));
        __nv_bfloat16* o = d_Bc + (size_t)u * K2;
        o[k] = hi; o[KTOT + k] = lo;
    }
}

// ---------------- HMMA GEMM, cp.async 3-stage, CTA 128x128, warp 32x64 ----------------
// Logical K' = 13824 as 3 terms [WhiBhi, WhiBlo, WloBhi] over dedup [hi,lo] storage.
// grid (9, 4, KSPLIT=12), 256 threads (8 warps: 4M x 2N). Epilogue staged via smem.
__global__ void __launch_bounds__(256, 2) gemm_hmma(void) {
    int n0 = blockIdx.x * 128;
    if (n0 >= d_Upad) return;                  // dedup early-exit
    int m0 = blockIdx.y * 128;
    int ks = blockIdx.z;
    int kq0 = ks * KQ;
    int aOff = kq0 - ((ks >= 4) ? KTOT : 0);   // Whi,Whi,Wlo
    int bOff = (ks >= 8) ? (kq0 - 2 * KTOT) : kq0;  // Bhi,Blo,Bhi

    extern __shared__ char smraw[];
    __nv_bfloat16* sm = (__nv_bfloat16*)smraw;
    uint32_t smBase = smem_u32(sm);

    int t = threadIdx.x;
    int wid = t >> 5, lane = t & 31;
    int wm = wid & 3, wn = wid >> 2;

    float acc[2][8][4];
    #pragma unroll
    for (int i = 0; i < 2; i++)
        #pragma unroll
        for (int j = 0; j < 8; j++)
            #pragma unroll
            for (int e = 0; e < 4; e++) acc[i][j][e] = 0.0f;

    int row = t >> 3, c16 = t & 7;
    const __nv_bfloat16* aG0 = d_Wc + (size_t)(m0 + row) * K2 + aOff + c16 * 8;
    const __nv_bfloat16* bG0 = d_Bc + (size_t)(n0 + row) * K2 + bOff + c16 * 8;
    uint32_t aS0 = smBase + 2 * (uint32_t)(row * ASTRIDE + c16 * 8);
    uint32_t bS0 = smBase + 2 * (uint32_t)(128 * ASTRIDE + row * ASTRIDE + c16 * 8);

    #define ISSUE(ch) do {                                                     \
        uint32_t so = 2u * (uint32_t)(((ch) % 3) * STG);                       \
        int ko = (ch) * BK;                                                    \
        _Pragma("unroll")                                                      \
        for (int i = 0; i < 4; i++)                                            \
            asm volatile("cp.async.cg.shared.global [%0], [%1], 16;"           \
                :: "r"(aS0 + so + 2u * (uint32_t)(i * 32 * ASTRIDE)),          \
                   "l"(aG0 + (size_t)i * 32 * K2 + ko) : "memory");            \
        _Pragma("unroll")                                                      \
        for (int i = 0; i < 4; i++)                                            \
            asm volatile("cp.async.cg.shared.global [%0], [%1], 16;"           \
                :: "r"(bS0 + so + 2u * (uint32_t)(i * 32 * ASTRIDE)),          \
                   "l"(bG0 + (size_t)i * 32 * K2 + ko) : "memory");            \
        asm volatile("cp.async.commit_group;" ::: "memory");                   \
    } while (0)

    ISSUE(0);
    ISSUE(1);

    for (int ch = 0; ch < NCH; ch++) {
        if (ch + 1 < NCH) asm volatile("cp.async.wait_group 1;" ::: "memory");
        else              asm volatile("cp.async.wait_group 0;" ::: "memory");
        __syncthreads();
        if (ch + 2 < NCH) ISSUE(ch + 2);

        uint32_t so = 2u * (uint32_t)((ch % 3) * STG);
        #pragma unroll
        for (int s = 0; s < 4; s++) {          // 4 k16 steps per BK=64
            int koff = s * 16;
            uint32_t a[2][4], b[4][4];
            #pragma unroll
            for (int tm = 0; tm < 2; tm++) {
                uint32_t addr = smBase + so + 2 * (uint32_t)(
                    (wm * 32 + tm * 16 + (lane & 15)) * ASTRIDE + koff + ((lane >> 4) << 3));
                asm volatile("ldmatrix.sync.aligned.m8n8.x4.shared.b16 {%0,%1,%2,%3}, [%4];"
                    : "=r"(a[tm][0]), "=r"(a[tm][1]), "=r"(a[tm][2]), "=r"(a[tm][3]) : "r"(addr));
            }
            #pragma unroll
            for (int p = 0; p < 4; p++) {
                int g = lane >> 3;
                int brow = wn * 64 + p * 16 + ((g >> 1) << 3) + (lane & 7);
                int kadd = (g & 1) << 3;
                uint32_t addr = smBase + so + 2 * (uint32_t)(
                    128 * ASTRIDE + brow * ASTRIDE + koff + kadd);
                asm volatile("ldmatrix.sync.aligned.m8n8.x4.shared.b16 {%0,%1,%2,%3}, [%4];"
                    : "=r"(b[p][0]), "=r"(b[p][1]), "=r"(b[p][2]), "=r"(b[p][3]) : "r"(addr));
            }
            #pragma unroll
            for (int tm = 0; tm < 2; tm++)
                #pragma unroll
                for (int tn = 0; tn < 8; tn++) {
                    int p = tn >> 1, h = (tn & 1) << 1;
                    asm volatile(
                        "mma.sync.aligned.m16n8k16.row.col.f32.bf16.bf16.f32 "
                        "{%0,%1,%2,%3}, {%4,%5,%6,%7}, {%8,%9}, {%0,%1,%2,%3};"
                        : "+f"(acc[tm][tn][0]), "+f"(acc[tm][tn][1]),
                          "+f"(acc[tm][tn][2]), "+f"(acc[tm][tn][3])
                        : "r"(a[tm][0]), "r"(a[tm][1]), "r"(a[tm][2]), "r"(a[tm][3]),
                          "r"(b[p][h]), "r"(b[p][h + 1]));
                }
        }
        __syncthreads();
    }

    // ---- staged epilogue: acc -> smem [u][m] (stride FST) -> coalesced gmem ----
    float* smF = (float*)smraw;    // 128*FST*4 = 67.6 KB <= 110.6 KB
    int g = lane >> 2, tq = lane & 3;
    #pragma unroll
    for (int tm = 0; tm < 2; tm++) {
        int rm = wm * 32 + tm * 16 + g;
        #pragma unroll
        for (int tn = 0; tn < 8; tn++) {
            int cn = wn * 64 + tn * 8 + tq * 2;
            smF[cn * FST + rm]           = acc[tm][tn][0];
            smF[(cn + 1) * FST + rm]     = acc[tm][tn][1];
            smF[cn * FST + rm + 8]       = acc[tm][tn][2];
            smF[(cn + 1) * FST + rm + 8] = acc[tm][tn][3];
        }
    }
    __syncthreads();
    float* hpBase = d_hp + (size_t)(ks * NU2 + n0) * CIN + m0;
    for (int i = t; i < 128 * 32; i += 256) {
        int u = i >> 5, m4 = (i & 31) << 2;
        float4 v = *(float4*)&smF[u * FST + m4];
        *(float4*)(hpBase + (size_t)u * CIN + m4) = v;
    }
}

// ---------------- per-column 1x1 conv dot (fused partial-reduce + bias + relu) ----------------
__global__ void coldot_kernel(const float* __restrict__ bw, const float* __restrict__ bb,
                              const float* __restrict__ sw, const float* __restrict__ sb,
                              const float* __restrict__ conv_b) {
    int col = blockIdx.x * 8 + (threadIdx.x >> 5);
    int lane = threadIdx.x & 31;
    int npos = d_nPos;
    int u;
    if (col < 512)      { int t = col >> 2;         u = (t < npos) ? 1 + col : 0; }
    else if (col < 768) { int t = (col - 512) >> 1; u = (t < npos) ? 1 + 4 * npos + (col - 512) : 0; }
    else                { int g = (col - 768) >> 1; u = (g < 256 - npos) ? 1 + 6 * npos + (col - 768) : 0; }
    if (u == 0) return;
    int meta = d_colMeta[col];
    const float* w;
    float b;
    if (meta < 36) { w = bw + meta * 512; b = bb[meta]; }
    else           { w = sw + (meta - 36) * 512; b = sb[meta - 36]; }
    const float4* wv = (const float4*)w;
    const float4* bias4 = (const float4*)conv_b;
    float s = 0.0f;
    for (int i = lane; i < 128; i += 32) {
        float4 a = bias4[i];
        #pragma unroll
        for (int ks = 0; ks < KSPLIT; ks++) {
            const float4* hp4 = (const float4*)(d_hp + (size_t)(ks * NU2 + u) * CIN);
            float4 hv = hp4[i];
            a.x += hv.x; a.y += hv.y; a.z += hv.z; a.w += hv.w;
        }
        a.x = fmaxf(a.x, 0.0f); a.y = fmaxf(a.y, 0.0f);
        a.z = fmaxf(a.z, 0.0f); a.w = fmaxf(a.w, 0.0f);
        float4 ww = wv[i];
        s += a.x * ww.x + a.y * ww.y + a.z * ww.z + a.w * ww.w;
    }
    #pragma unroll
    for (int o = 16; o > 0; o >>= 1) s += __shfl_xor_sync(0xFFFFFFFFu, s, o);
    if (lane == 0) d_val[col] = fmaxf(s + b, 0.0f);
}

// ---------------- loss ----------------
__global__ void loss_kernel(const float* __restrict__ target, float* __restrict__ out) {
    __shared__ float rce[256], rsl[256], rvc[256];
    int t = threadIdx.x;
    float ce = 0.0f, sl = 0.0f, vc = 0.0f;
    if (t < 128 && d_posValid[t]) {
        float s0 = d_val[512 + 2 * t], s1 = d_val[512 + 2 * t + 1];
        float m = fmaxf(s0, s1);
        float lse = m + logf(expf(s0 - m) + expf(s1 - m));
        ce += lse - s0;
        vc += 1.0f;
        int p = d_posIdx[t];
        int k = p % 9;
        int q = p / 9;
        int wq = q & 127;
        int hq = q >> 7;
        float ax1 = hq * STEP, ay1 = wq * STEP;
        float aw = d_whw[k], ah = d_whh[k];
        float acx = ax1 + aw * 0.5f, acy = ay1 + ah * 0.5f;
        float4 tb = ((const float4*)target)[d_tgtIdx[p]];
        float bw_ = tb.z - tb.x, bh_ = tb.w - tb.y;
        float bcx = tb.x + bw_ * 0.5f, bcy = tb.y + bh_ * 0.5f;
        float tr[4] = {(bcx - acx) / aw, (bcy - acy) / ah,
                       logf(bw_ / aw), logf(bh_ / ah)};
        #pragma unroll
        for (int e = 0; e < 4; e++) {
            float dd = d_val[4 * t + e] - tr[e];
            float ad = fabsf(dd);
            sl += (ad < 1.0f) ? 0.5f * dd * dd : (ad - 0.5f);
        }
    }
    if (t < 256 && d_negValid[t]) {
        float s0 = d_val[768 + 2 * t], s1 = d_val[768 + 2 * t + 1];
        float m = fmaxf(s0, s1);
        float lse = m + logf(expf(s0 - m) + expf(s1 - m));
        ce += lse - s1;
        vc += 1.0f;
    }
    rce[t] = ce; rsl[t] = sl; rvc[t] = vc;
    __syncthreads();
    for (int s2 = 128; s2 > 0; s2 >>= 1) {
        if (t < s2) { rce[t] += rce[t + s2]; rsl[t] += rsl[t + s2]; rvc[t] += rvc[t + s2]; }
        __syncthreads();
    }
    if (t == 0) {
        float np = (float)d_nPos;
        float score_loss = rce[0] / fmaxf(rvc[0], 1.0f);
        float reg_loss = rsl[0] / fmaxf(np * 4.0f, 1.0f);
        out[0] = score_loss + 10.0f * reg_loss;
    }
}

// ---------------- launch ----------------
extern "C" void kernel_launch(void* const* d_in, const int* in_sizes, int n_in,
                              void* d_out, int out_size) {
    const float* x       = (const float*)d_in[0];
    const float* target  = (const float*)d_in[1];
    const float* conv_w  = (const float*)d_in[2];
    const float* conv_b  = (const float*)d_in[3];
    const float* bbox_w  = (const float*)d_in[4];
    const float* bbox_b  = (const float*)d_in[5];
    const float* score_w = (const float*)d_in[6];
    const float* score_b = (const float*)d_in[7];
    float* out = (float*)d_out;

    // smem: 3 stages x 256*72 halves * 2B = 110592 B (epilogue reuses 67.6 KB of it)
    const int DSMEM = 3 * STG * 2;
    cudaFuncSetAttribute(gemm_hmma, cudaFuncAttributeMaxDynamicSharedMemorySize, DSMEM);

    iou_kernel<<<NBLK, 256>>>(target);
    selection_kernel<<<1, 1024>>>();
    prep_kernel<<<WBLK + GBLK, 256>>>(conv_w, x);
    gemm_hmma<<<dim3(NU2 / 128, CIN / 128, KSPLIT), 256, DSMEM>>>();
    coldot_kernel<<<NCOL / 8, 256>>>(bbox_w, bbox_b, score_w, score_b, conv_b);
    loss_kernel<<<1, 256>>>(target, out);
}